// round 2
// baseline (speedup 1.0000x reference)
#include <cuda_runtime.h>
#include <math.h>

#define T_STEPS 512
#define B_SZ    128
#define BT      (B_SZ * T_STEPS)
#define OUT_D   1442
#define NCTA    128

// ---------------- scratch (static device globals; no allocation) ----------------
__device__ __align__(16) float g_oproj[BT * 256];   // obs @ W1o + post_b1, [B][T][256]
__device__ __align__(16) float g_hid  [BT * 256];   // scratch for phase C
__device__ __align__(16) float g_WihT [768 * 304];  // W_ih transposed: [n][k]
__device__ __align__(16) float g_WhhT [768 * 256];  // W_hh transposed: [n][k]
__device__ __align__(16) float g_hidstep[B_SZ * 256]; // per-step posterior hidden
__device__ unsigned g_bar_cnt;
__device__ unsigned g_bar_gen;

__device__ __forceinline__ float sigmoidf_(float x) { return 1.f / (1.f + expf(-x)); }
__device__ __forceinline__ float softplusf_(float x) {
    return fmaxf(x, 0.f) + log1pf(expf(-fabsf(x)));
}

// ---------------- prep: transpose GRU weights once ----------------
__global__ void prep_kernel(const float* __restrict__ W_ih, const float* __restrict__ W_hh) {
    int idx = blockIdx.x * 256 + threadIdx.x;
    const int n1 = 768 * 304;
    if (idx < n1) {
        int n = idx / 304, k = idx - n * 304;
        g_WihT[idx] = W_ih[k * 768 + n];
    } else {
        int r = idx - n1;            // exact grid: r < 768*256
        int n = r >> 8, k = r & 255;
        g_WhhT[r] = W_hh[k * 768 + n];
    }
}

// ---------------- grid barrier (sense-reversing, L2 atomics) ----------------
__device__ __forceinline__ void grid_bar() {
    __threadfence();
    __syncthreads();
    if (threadIdx.x == 0) {
        unsigned gen = atomicAdd(&g_bar_gen, 0u);
        if (atomicAdd(&g_bar_cnt, 1u) == NCTA - 1) {
            g_bar_cnt = 0;
            __threadfence();
            atomicAdd(&g_bar_gen, 1u);
        } else {
            while (atomicAdd(&g_bar_gen, 0u) == gen) { __nanosleep(128); }
        }
    }
    __syncthreads();
    __threadfence();
}

// ---------------- persistent scan kernel ----------------
// 128 CTAs x 256 threads. CTA c: jt = c & 15 (16 h-cols), bt = c >> 4 (16 batch rows).
// SMEM-resident: GRU weight slice (16x1680), W1h slice [jl][260], W2 full, b2.
// Per step: A) GRU -> h_t ; bar ; B) hid=relu(h@W1h+oproj) ; bar ; C) o64=hid@W2, sample ; bar.
#define SM_WGRU 0
#define SM_W1H  26880
#define SM_W2   (26880 + 16*260)            // 31040
#define SM_B2   (SM_W2 + 16384)             // 47424
#define SM_XS   (SM_B2 + 64)                // 47488
#define SM_FLOATS (SM_XS + 16*305)          // 52368
#define SMEM_BYTES (SM_FLOATS * 4)          // 209472

__global__ void __launch_bounds__(256, 1) scan_kernel(
    float* __restrict__ out, const float* __restrict__ act_seq,
    const float* __restrict__ eps,
    const float* __restrict__ b_ih, const float* __restrict__ b_hh,
    const float* __restrict__ post_W1, const float* __restrict__ post_W2,
    const float* __restrict__ post_b2)
{
    extern __shared__ float sm[];
    float* wgru = sm + SM_WGRU;
    float* w1hs = sm + SM_W1H;   // [jl][k] stride 260
    float* w2s  = sm + SM_W2;    // [k][o] 256x64
    float* b2s  = sm + SM_B2;
    float* xs   = sm + SM_XS;    // reused: xs[16][305] / hs[16][260] / C bufs

    const int tid = threadIdx.x;
    const int c   = blockIdx.x;
    const int jt  = c & 15;
    const int bt  = c >> 4;
    const int jl  = tid >> 4;
    const int bl  = tid & 15;
    const int jc  = jt * 16 + jl;
    const int b_a = bt * 16 + bl;      // batch row for phases A/B

    // ---- preload weights into SMEM (once) ----
    for (int idx = tid; idx < 16 * 1680; idx += 256) {
        int j_ = idx / 1680, r = idx - j_ * 1680;
        int j = jt * 16 + j_;
        float v;
        if (r < 912) { int g = r / 304, k = r - g * 304; v = g_WihT[(size_t)(g * 256 + j) * 304 + k]; }
        else { int r2 = r - 912; int g = r2 >> 8, k = r2 & 255; v = g_WhhT[(size_t)(g * 256 + j) * 256 + k]; }
        wgru[idx] = v;
    }
    for (int idx = tid; idx < 16 * 256; idx += 256) {
        int j_ = idx >> 8, k = idx & 255;
        w1hs[j_ * 260 + k] = post_W1[(size_t)k * 256 + jt * 16 + j_];
    }
    for (int idx = tid; idx < 16384; idx += 256) w2s[idx] = post_W2[idx];
    if (tid < 64) b2s[tid] = post_b2[tid];
    __syncthreads();

    const float bir = b_ih[jc], biz = b_ih[jc + 256], bin_ = b_ih[jc + 512];
    const float bhr = b_hh[jc], bhz = b_hh[jc + 256], bhn = b_hh[jc + 512];

    for (int t = 0; t < T_STEPS; t++) {
        // ================= Phase A: GRU (t>=1) or zero-init h (t==0) =================
        if (t == 0) {
            out[((size_t)b_a * T_STEPS) * OUT_D + jc] = 0.f;
        } else {
            for (int idx = tid; idx < 16 * 304; idx += 256) {
                int bl_ = idx / 304, k = idx - bl_ * 304;
                int b = bt * 16 + bl_;
                float v = (k < 288)
                    ? out[((size_t)b * T_STEPS + (t - 1)) * OUT_D + k]
                    : act_seq[((size_t)b * T_STEPS + (t - 1)) * 16 + (k - 288)];
                xs[bl_ * 305 + k] = v;
            }
            __syncthreads();

            const float4* wir = (const float4*)(wgru + jl * 1680);
            const float4* wiz = (const float4*)(wgru + jl * 1680 + 304);
            const float4* win = (const float4*)(wgru + jl * 1680 + 608);
            const float4* whr = (const float4*)(wgru + jl * 1680 + 912);
            const float4* whz = (const float4*)(wgru + jl * 1680 + 1168);
            const float4* whn = (const float4*)(wgru + jl * 1680 + 1424);
            const float* xrow = xs + bl * 305;

            float4 air = {0,0,0,0}, aiz = air, ain = air, ahr = air, ahz = air, ahn = air;
#pragma unroll 4
            for (int k4 = 0; k4 < 64; k4++) {
                float x0 = xrow[4*k4], x1 = xrow[4*k4+1], x2 = xrow[4*k4+2], x3 = xrow[4*k4+3];
                float4 a = wir[k4], b_ = wiz[k4], cc = win[k4];
                float4 d = whr[k4], e = whz[k4], f = whn[k4];
                air.x = fmaf(x0,a.x,air.x);  air.y = fmaf(x1,a.y,air.y);
                air.z = fmaf(x2,a.z,air.z);  air.w = fmaf(x3,a.w,air.w);
                aiz.x = fmaf(x0,b_.x,aiz.x); aiz.y = fmaf(x1,b_.y,aiz.y);
                aiz.z = fmaf(x2,b_.z,aiz.z); aiz.w = fmaf(x3,b_.w,aiz.w);
                ain.x = fmaf(x0,cc.x,ain.x); ain.y = fmaf(x1,cc.y,ain.y);
                ain.z = fmaf(x2,cc.z,ain.z); ain.w = fmaf(x3,cc.w,ain.w);
                ahr.x = fmaf(x0,d.x,ahr.x);  ahr.y = fmaf(x1,d.y,ahr.y);
                ahr.z = fmaf(x2,d.z,ahr.z);  ahr.w = fmaf(x3,d.w,ahr.w);
                ahz.x = fmaf(x0,e.x,ahz.x);  ahz.y = fmaf(x1,e.y,ahz.y);
                ahz.z = fmaf(x2,e.z,ahz.z);  ahz.w = fmaf(x3,e.w,ahz.w);
                ahn.x = fmaf(x0,f.x,ahn.x);  ahn.y = fmaf(x1,f.y,ahn.y);
                ahn.z = fmaf(x2,f.z,ahn.z);  ahn.w = fmaf(x3,f.w,ahn.w);
            }
#pragma unroll
            for (int k4 = 64; k4 < 76; k4++) {  // z,a feed only input gates
                float x0 = xrow[4*k4], x1 = xrow[4*k4+1], x2 = xrow[4*k4+2], x3 = xrow[4*k4+3];
                float4 a = wir[k4], b_ = wiz[k4], cc = win[k4];
                air.x = fmaf(x0,a.x,air.x);  air.y = fmaf(x1,a.y,air.y);
                air.z = fmaf(x2,a.z,air.z);  air.w = fmaf(x3,a.w,air.w);
                aiz.x = fmaf(x0,b_.x,aiz.x); aiz.y = fmaf(x1,b_.y,aiz.y);
                aiz.z = fmaf(x2,b_.z,aiz.z); aiz.w = fmaf(x3,b_.w,aiz.w);
                ain.x = fmaf(x0,cc.x,ain.x); ain.y = fmaf(x1,cc.y,ain.y);
                ain.z = fmaf(x2,cc.z,ain.z); ain.w = fmaf(x3,cc.w,ain.w);
            }
            float sir = air.x+air.y+air.z+air.w + bir;
            float siz = aiz.x+aiz.y+aiz.z+aiz.w + biz;
            float sin_= ain.x+ain.y+ain.z+ain.w + bin_;
            float shr = ahr.x+ahr.y+ahr.z+ahr.w + bhr;
            float shz = ahz.x+ahz.y+ahz.z+ahz.w + bhz;
            float shn = ahn.x+ahn.y+ahn.z+ahn.w + bhn;

            float r  = sigmoidf_(sir + shr);
            float zg = sigmoidf_(siz + shz);
            float n  = tanhf(sin_ + r * shn);
            float hprev = xrow[jc];
            float hnew  = (1.f - zg) * n + zg * hprev;
            out[((size_t)b_a * T_STEPS + t) * OUT_D + jc] = hnew;
        }
        grid_bar();

        // ================= Phase B: hid = relu(h_t @ W1h + oproj) =================
        {
            float* hs = xs;   // [16][260]
            for (int idx = tid; idx < 16 * 256; idx += 256) {
                int bl_ = idx >> 8, k = idx & 255;
                hs[bl_ * 260 + k] = out[((size_t)(bt * 16 + bl_) * T_STEPS + t) * OUT_D + k];
            }
            __syncthreads();
            const float4* hv = (const float4*)(hs + bl * 260);
            const float4* wv = (const float4*)(w1hs + jl * 260);
            float4 a = {0,0,0,0};
#pragma unroll 8
            for (int k4 = 0; k4 < 64; k4++) {
                float4 h4 = hv[k4], w4 = wv[k4];
                a.x = fmaf(h4.x, w4.x, a.x); a.y = fmaf(h4.y, w4.y, a.y);
                a.z = fmaf(h4.z, w4.z, a.z); a.w = fmaf(h4.w, w4.w, a.w);
            }
            float acc = a.x + a.y + a.z + a.w
                      + g_oproj[((size_t)b_a * T_STEPS + t) * 256 + jc];
            g_hidstep[b_a * 256 + jc] = fmaxf(acc, 0.f);
        }
        grid_bar();

        // ================= Phase C: o64 = hid @ W2 + b2, sample, write =================
        {
            const int b = c;                  // CTA id = batch row
            float* hbuf = xs;                 // [256]
            float* part = xs + 256;           // [256]
            float* o64  = xs + 512;           // [64]
            if (tid < 256) hbuf[tid] = g_hidstep[b * 256 + tid];
            __syncthreads();
            const int q = tid >> 6, o = tid & 63;
            float acc = 0.f;
#pragma unroll 16
            for (int k = 0; k < 64; k++)
                acc = fmaf(hbuf[q * 64 + k], w2s[(q * 64 + k) * 64 + o], acc);
            part[tid] = acc;
            __syncthreads();
            if (tid < 64)
                o64[tid] = part[tid] + part[64 + tid] + part[128 + tid] + part[192 + tid] + b2s[tid];
            __syncthreads();
            if (tid < 32) {
                int s = tid;
                float pm = o64[s];
                float ps = softplusf_(o64[s + 32]) + 0.1f;
                float e  = eps[((size_t)t * B_SZ + b) * 32 + s];
                size_t base = ((size_t)b * T_STEPS + t) * OUT_D;
                out[base + 352 + s] = pm;
                out[base + 384 + s] = ps;
                out[base + 256 + s] = fmaf(ps, e, pm);
            }
        }
        grid_bar();
    }
}

// ---------------- generic fp32 tiled GEMM: C = act(A@W + bias) ----------------
__global__ void gemm_kernel(int M, int N, int K,
                            const float* __restrict__ A, int lda,
                            const float* __restrict__ W,
                            const float* __restrict__ bias,
                            float* __restrict__ C, int ldc, int act)
{
    __shared__ __align__(16) float As[16][132];
    __shared__ __align__(16) float Ws[16][64];
    const int tid = threadIdx.x;
    const int tx = tid & 15;
    const int ty = tid >> 4;
    const int rowBase = blockIdx.y * 128;
    const int colBase = blockIdx.x * 64;

    float acc[8][4];
#pragma unroll
    for (int i = 0; i < 8; i++)
#pragma unroll
        for (int j = 0; j < 4; j++) acc[i][j] = 0.f;

    const int ka = tid & 15;
    const int ra = tid >> 4;
    const int nw = tid & 63;
    const int kw = tid >> 6;

    for (int k0 = 0; k0 < K; k0 += 16) {
#pragma unroll
        for (int p = 0; p < 8; p++)
            As[ka][ra + p * 16] = A[(size_t)(rowBase + ra + p * 16) * lda + k0 + ka];
#pragma unroll
        for (int p = 0; p < 4; p++)
            Ws[kw + p * 4][nw] = W[(size_t)(k0 + kw + p * 4) * N + colBase + nw];
        __syncthreads();
#pragma unroll
        for (int k = 0; k < 16; k++) {
            float4 av0 = *(const float4*)&As[k][ty * 8];
            float4 av1 = *(const float4*)&As[k][ty * 8 + 4];
            float a[8] = {av0.x, av0.y, av0.z, av0.w, av1.x, av1.y, av1.z, av1.w};
            float4 wv = *(const float4*)&Ws[k][tx * 4];
            float w[4] = {wv.x, wv.y, wv.z, wv.w};
#pragma unroll
            for (int i = 0; i < 8; i++)
#pragma unroll
                for (int j = 0; j < 4; j++) acc[i][j] = fmaf(a[i], w[j], acc[i][j]);
        }
        __syncthreads();
    }
#pragma unroll
    for (int i = 0; i < 8; i++) {
        int r = rowBase + ty * 8 + i;
#pragma unroll
        for (int j = 0; j < 4; j++) {
            int cc = colBase + tx * 4 + j;
            float v = acc[i][j];
            if (bias) v += bias[cc];
            if (act == 1) v = fmaxf(v, 0.f);
            else if (act == 2 && cc >= 32) v = softplusf_(v) + 0.1f;
            C[(size_t)r * ldc + cc] = v;
        }
    }
}

// ---------------- GEMV (N=1) ----------------
__global__ void gemv_kernel(const float* __restrict__ A, const float* __restrict__ w,
                            const float* __restrict__ bias, float* __restrict__ C, int act)
{
    const int warp = threadIdx.x >> 5, lane = threadIdx.x & 31;
    const int row = blockIdx.x * 8 + warp;
    const float* a = A + (size_t)row * 256;
    float acc = 0.f;
#pragma unroll
    for (int i = 0; i < 8; i++) acc = fmaf(a[lane + 32 * i], w[lane + 32 * i], acc);
#pragma unroll
    for (int off = 16; off; off >>= 1) acc += __shfl_xor_sync(0xffffffffu, acc, off);
    if (lane == 0) {
        float v = acc + bias[0];
        if (act == 3) v = sigmoidf_(v);
        C[(size_t)row * OUT_D] = v;
    }
}

// ---------------- driver ----------------
extern "C" void kernel_launch(void* const* d_in, const int* in_sizes, int n_in,
                              void* d_out, int out_size)
{
    const float* obs      = (const float*)d_in[0];
    const float* act      = (const float*)d_in[1];
    const float* eps      = (const float*)d_in[2];
    const float* prior_W1 = (const float*)d_in[3];
    const float* prior_b1 = (const float*)d_in[4];
    const float* prior_W2 = (const float*)d_in[5];
    const float* prior_b2 = (const float*)d_in[6];
    const float* post_W1  = (const float*)d_in[7];
    const float* post_b1  = (const float*)d_in[8];
    const float* post_W2  = (const float*)d_in[9];
    const float* post_b2  = (const float*)d_in[10];
    const float* W_ih     = (const float*)d_in[11];
    const float* b_ih     = (const float*)d_in[12];
    const float* W_hh     = (const float*)d_in[13];
    const float* b_hh     = (const float*)d_in[14];
    const float* dobs_W1  = (const float*)d_in[15];
    const float* dobs_b1  = (const float*)d_in[16];
    const float* dobs_W2  = (const float*)d_in[17];
    const float* dobs_b2  = (const float*)d_in[18];
    const float* drew_W1  = (const float*)d_in[19];
    const float* drew_b1  = (const float*)d_in[20];
    const float* drew_W2  = (const float*)d_in[21];
    const float* drew_b2  = (const float*)d_in[22];
    const float* dcont_W1 = (const float*)d_in[23];
    const float* dcont_b1 = (const float*)d_in[24];
    const float* dcont_W2 = (const float*)d_in[25];
    const float* dcont_b2 = (const float*)d_in[26];
    float* out = (float*)d_out;

    float *oproj_p = nullptr, *hid_p = nullptr;
    cudaGetSymbolAddress((void**)&oproj_p, g_oproj);
    cudaGetSymbolAddress((void**)&hid_p, g_hid);

    static int smem_set = 0;
    if (!smem_set) {
        cudaFuncSetAttribute(scan_kernel, cudaFuncAttributeMaxDynamicSharedMemorySize, SMEM_BYTES);
        smem_set = 1;
    }

    prep_kernel<<<1680, 256>>>(W_ih, W_hh);

    // Phase A: o_proj = obs @ W1o + post_b1  (rows 256..1279 of post_W1)
    gemm_kernel<<<dim3(4, BT / 128), 256>>>(BT, 256, 1024, obs, 1024,
                                            post_W1 + 256 * 256, post_b1,
                                            oproj_p, 256, 0);

    // Phase B: persistent sequential scan (GRU + posterior + sample)
    scan_kernel<<<NCTA, 256, SMEM_BYTES>>>(out, act, eps, b_ih, b_hh,
                                           post_W1, post_W2, post_b2);

    // Phase C: prior + decoders, batch-parallel over all (b,t)
    gemm_kernel<<<dim3(4, BT / 128), 256>>>(BT, 256, 256, out, OUT_D,
                                            prior_W1, prior_b1, hid_p, 256, 1);
    gemm_kernel<<<dim3(1, BT / 128), 256>>>(BT, 64, 256, hid_p, 256,
                                            prior_W2, prior_b2, out + 288, OUT_D, 2);
    gemm_kernel<<<dim3(4, BT / 128), 256>>>(BT, 256, 288, out, OUT_D,
                                            dobs_W1, dobs_b1, hid_p, 256, 1);
    gemm_kernel<<<dim3(16, BT / 128), 256>>>(BT, 1024, 256, hid_p, 256,
                                             dobs_W2, dobs_b2, out + 416, OUT_D, 0);
    gemm_kernel<<<dim3(4, BT / 128), 256>>>(BT, 256, 288, out, OUT_D,
                                            drew_W1, drew_b1, hid_p, 256, 1);
    gemv_kernel<<<BT / 8, 256>>>(hid_p, drew_W2, drew_b2, out + 1440, 0);
    gemm_kernel<<<dim3(4, BT / 128), 256>>>(BT, 256, 288, out, OUT_D,
                                            dcont_W1, dcont_b1, hid_p, 256, 1);
    gemv_kernel<<<BT / 8, 256>>>(hid_p, dcont_W2, dcont_b2, out + 1441, 3);
}

// round 3
// speedup vs baseline: 1.2373x; 1.2373x over previous
#include <cuda_runtime.h>
#include <math.h>

#define T_STEPS 512
#define B_SZ    128
#define BT      (B_SZ * T_STEPS)
#define OUT_D   1442
#define NCTA    128

// ---------------- scratch (static device globals; no allocation) ----------------
__device__ __align__(16) float g_oproj[BT * 256];     // obs @ W1o + post_b1, [B][T][256]
__device__ __align__(16) float g_hid3 [(size_t)BT * 1024]; // merged decoder hidden
__device__ __align__(16) float g_WihT [768 * 304];    // W_ih transposed: [n][k]
__device__ __align__(16) float g_WhhT [768 * 256];    // W_hh transposed: [n][k]
__device__ __align__(16) float g_Wcat [288 * 1024];   // merged decoder L1 weights
__device__ __align__(16) float g_bcat [1024];
__device__ __align__(16) float g_hidstep[B_SZ * 256]; // per-step posterior hidden
__device__ __align__(16) float g_state[B_SZ * 288];   // compact h(256)|z(32)
__device__ unsigned g_cnt;

__device__ __forceinline__ float sigmoidf_(float x) { return 1.f / (1.f + expf(-x)); }
__device__ __forceinline__ float softplusf_(float x) {
    return fmaxf(x, 0.f) + log1pf(expf(-fabsf(x)));
}

// ---------------- prep: transpose GRU weights, reset barrier ----------------
__global__ void prep_kernel(const float* __restrict__ W_ih, const float* __restrict__ W_hh) {
    if (blockIdx.x == 0 && threadIdx.x == 0) g_cnt = 0u;
    int idx = blockIdx.x * 256 + threadIdx.x;
    const int n1 = 768 * 304;
    if (idx < n1) {
        int n = idx / 304, k = idx - n * 304;
        g_WihT[idx] = W_ih[k * 768 + n];
    } else {
        int r = idx - n1;            // exact grid: r < 768*256
        int n = r >> 8, k = r & 255;
        g_WhhT[r] = W_hh[k * 768 + n];
    }
}

// build Wcat[288][1024]: cols 0..255 prior_W1 (z-rows zeroed), 256..511 dobs,
// 512..767 drew, 768..1023 dcont. Also bias concat.
__global__ void prep2_kernel(const float* __restrict__ prior_W1, const float* __restrict__ prior_b1,
                             const float* __restrict__ dobs_W1,  const float* __restrict__ dobs_b1,
                             const float* __restrict__ drew_W1,  const float* __restrict__ drew_b1,
                             const float* __restrict__ dcont_W1, const float* __restrict__ dcont_b1)
{
    int idx = blockIdx.x * 256 + threadIdx.x;      // 288*1024 grid
    int k = idx >> 10, j = idx & 1023;
    int g = j >> 8, jj = j & 255;
    float v;
    if (g == 0)      v = (k < 256) ? prior_W1[k * 256 + jj] : 0.f;
    else if (g == 1) v = dobs_W1[(size_t)k * 256 + jj];
    else if (g == 2) v = drew_W1[(size_t)k * 256 + jj];
    else             v = dcont_W1[(size_t)k * 256 + jj];
    g_Wcat[idx] = v;
    if (idx < 1024) {
        float b;
        if (g == 0)      b = prior_b1[jj];
        else if (g == 1) b = dobs_b1[jj];
        else if (g == 2) b = drew_b1[jj];
        else             b = dcont_b1[jj];
        g_bcat[idx] = b;
    }
}

// ---------------- fast grid barrier: monotonic counter, plain-load poll ----------------
__device__ __forceinline__ void grid_bar(unsigned target) {
    __syncthreads();
    if (threadIdx.x == 0) {
        __threadfence();
        atomicAdd(&g_cnt, 1u);
        volatile unsigned* p = &g_cnt;
        unsigned v;
        do { v = *p; } while (v < target);
        __threadfence();
    }
    __syncthreads();
}

// ---------------- persistent scan kernel ----------------
// 128 CTAs x 256 threads. CTA c: jt = c & 15 (16 h-cols), bt = c >> 4 (16 batch rows).
#define SM_WGRU 0
#define SM_W1H  26880
#define SM_W2   (26880 + 16*260)            // 31040
#define SM_B2   (SM_W2 + 16384)             // 47424
#define SM_XS   (SM_B2 + 64)                // 47488
#define SM_FLOATS (SM_XS + 16*305)          // 52368
#define SMEM_BYTES (SM_FLOATS * 4)          // 209472

__global__ void __launch_bounds__(256, 1) scan_kernel(
    float* __restrict__ out, const float* __restrict__ act_seq,
    const float* __restrict__ eps,
    const float* __restrict__ b_ih, const float* __restrict__ b_hh,
    const float* __restrict__ post_W1, const float* __restrict__ post_W2,
    const float* __restrict__ post_b2)
{
    extern __shared__ float sm[];
    float* wgru = sm + SM_WGRU;
    float* w1hs = sm + SM_W1H;   // [jl][k] stride 260
    float* w2s  = sm + SM_W2;    // [k][o] 256x64
    float* b2s  = sm + SM_B2;
    float* xs   = sm + SM_XS;    // reused: xs[16][305] / hs[16][260] / C bufs

    const int tid = threadIdx.x;
    const int c   = blockIdx.x;
    const int jt  = c & 15;
    const int bt  = c >> 4;
    const int jl  = tid >> 4;
    const int bl  = tid & 15;
    const int jc  = jt * 16 + jl;
    const int b_a = bt * 16 + bl;

    // ---- preload weights into SMEM (once) ----
    for (int idx = tid; idx < 16 * 1680; idx += 256) {
        int j_ = idx / 1680, r = idx - j_ * 1680;
        int j = jt * 16 + j_;
        float v;
        if (r < 912) { int g = r / 304, k = r - g * 304; v = g_WihT[(size_t)(g * 256 + j) * 304 + k]; }
        else { int r2 = r - 912; int g = r2 >> 8, k = r2 & 255; v = g_WhhT[(size_t)(g * 256 + j) * 256 + k]; }
        wgru[idx] = v;
    }
    for (int idx = tid; idx < 16 * 256; idx += 256) {
        int j_ = idx >> 8, k = idx & 255;
        w1hs[j_ * 260 + k] = post_W1[(size_t)k * 256 + jt * 16 + j_];
    }
    for (int idx = tid; idx < 16384; idx += 256) w2s[idx] = post_W2[idx];
    if (tid < 64) b2s[tid] = post_b2[tid];
    __syncthreads();

    const float bir = b_ih[jc], biz = b_ih[jc + 256], bin_ = b_ih[jc + 512];
    const float bhr = b_hh[jc], bhz = b_hh[jc + 256], bhn = b_hh[jc + 512];

    unsigned barv = 0;

    for (int t = 0; t < T_STEPS; t++) {
        // ================= Phase A: GRU (t>=1) or zero-init h (t==0) =================
        if (t == 0) {
            out[((size_t)b_a * T_STEPS) * OUT_D + jc] = 0.f;
            g_state[b_a * 288 + jc] = 0.f;
        } else {
            for (int idx = tid; idx < 16 * 304; idx += 256) {
                int bl_ = idx / 304, k = idx - bl_ * 304;
                int b = bt * 16 + bl_;
                float v = (k < 288)
                    ? g_state[b * 288 + k]
                    : act_seq[((size_t)b * T_STEPS + (t - 1)) * 16 + (k - 288)];
                xs[bl_ * 305 + k] = v;
            }
            __syncthreads();

            const float4* wir = (const float4*)(wgru + jl * 1680);
            const float4* wiz = (const float4*)(wgru + jl * 1680 + 304);
            const float4* win = (const float4*)(wgru + jl * 1680 + 608);
            const float4* whr = (const float4*)(wgru + jl * 1680 + 912);
            const float4* whz = (const float4*)(wgru + jl * 1680 + 1168);
            const float4* whn = (const float4*)(wgru + jl * 1680 + 1424);
            const float* xrow = xs + bl * 305;

            float4 air = {0,0,0,0}, aiz = air, ain = air, ahr = air, ahz = air, ahn = air;
#pragma unroll 4
            for (int k4 = 0; k4 < 64; k4++) {
                float x0 = xrow[4*k4], x1 = xrow[4*k4+1], x2 = xrow[4*k4+2], x3 = xrow[4*k4+3];
                float4 a = wir[k4], b_ = wiz[k4], cc = win[k4];
                float4 d = whr[k4], e = whz[k4], f = whn[k4];
                air.x = fmaf(x0,a.x,air.x);  air.y = fmaf(x1,a.y,air.y);
                air.z = fmaf(x2,a.z,air.z);  air.w = fmaf(x3,a.w,air.w);
                aiz.x = fmaf(x0,b_.x,aiz.x); aiz.y = fmaf(x1,b_.y,aiz.y);
                aiz.z = fmaf(x2,b_.z,aiz.z); aiz.w = fmaf(x3,b_.w,aiz.w);
                ain.x = fmaf(x0,cc.x,ain.x); ain.y = fmaf(x1,cc.y,ain.y);
                ain.z = fmaf(x2,cc.z,ain.z); ain.w = fmaf(x3,cc.w,ain.w);
                ahr.x = fmaf(x0,d.x,ahr.x);  ahr.y = fmaf(x1,d.y,ahr.y);
                ahr.z = fmaf(x2,d.z,ahr.z);  ahr.w = fmaf(x3,d.w,ahr.w);
                ahz.x = fmaf(x0,e.x,ahz.x);  ahz.y = fmaf(x1,e.y,ahz.y);
                ahz.z = fmaf(x2,e.z,ahz.z);  ahz.w = fmaf(x3,e.w,ahz.w);
                ahn.x = fmaf(x0,f.x,ahn.x);  ahn.y = fmaf(x1,f.y,ahn.y);
                ahn.z = fmaf(x2,f.z,ahn.z);  ahn.w = fmaf(x3,f.w,ahn.w);
            }
#pragma unroll
            for (int k4 = 64; k4 < 76; k4++) {  // z,a feed only input gates
                float x0 = xrow[4*k4], x1 = xrow[4*k4+1], x2 = xrow[4*k4+2], x3 = xrow[4*k4+3];
                float4 a = wir[k4], b_ = wiz[k4], cc = win[k4];
                air.x = fmaf(x0,a.x,air.x);  air.y = fmaf(x1,a.y,air.y);
                air.z = fmaf(x2,a.z,air.z);  air.w = fmaf(x3,a.w,air.w);
                aiz.x = fmaf(x0,b_.x,aiz.x); aiz.y = fmaf(x1,b_.y,aiz.y);
                aiz.z = fmaf(x2,b_.z,aiz.z); aiz.w = fmaf(x3,b_.w,aiz.w);
                ain.x = fmaf(x0,cc.x,ain.x); ain.y = fmaf(x1,cc.y,ain.y);
                ain.z = fmaf(x2,cc.z,ain.z); ain.w = fmaf(x3,cc.w,ain.w);
            }
            float sir = air.x+air.y+air.z+air.w + bir;
            float siz = aiz.x+aiz.y+aiz.z+aiz.w + biz;
            float sin_= ain.x+ain.y+ain.z+ain.w + bin_;
            float shr = ahr.x+ahr.y+ahr.z+ahr.w + bhr;
            float shz = ahz.x+ahz.y+ahz.z+ahz.w + bhz;
            float shn = ahn.x+ahn.y+ahn.z+ahn.w + bhn;

            float r  = sigmoidf_(sir + shr);
            float zg = sigmoidf_(siz + shz);
            float n  = tanhf(sin_ + r * shn);
            float hprev = xrow[jc];
            float hnew  = (1.f - zg) * n + zg * hprev;
            out[((size_t)b_a * T_STEPS + t) * OUT_D + jc] = hnew;
            g_state[b_a * 288 + jc] = hnew;
        }
        grid_bar(barv += NCTA);

        // ================= Phase B: hid = relu(h_t @ W1h + oproj) =================
        {
            float* hs = xs;   // [16][260]
            for (int idx = tid; idx < 16 * 64; idx += 256) {   // float4 loads
                int bl_ = idx >> 6, k4 = idx & 63;
                float4 v = *(const float4*)(g_state + (bt * 16 + bl_) * 288 + k4 * 4);
                *(float4*)(hs + bl_ * 260 + k4 * 4) = v;
            }
            __syncthreads();
            const float4* hv = (const float4*)(hs + bl * 260);
            const float4* wv = (const float4*)(w1hs + jl * 260);
            float4 a = {0,0,0,0};
#pragma unroll 8
            for (int k4 = 0; k4 < 64; k4++) {
                float4 h4 = hv[k4], w4 = wv[k4];
                a.x = fmaf(h4.x, w4.x, a.x); a.y = fmaf(h4.y, w4.y, a.y);
                a.z = fmaf(h4.z, w4.z, a.z); a.w = fmaf(h4.w, w4.w, a.w);
            }
            float acc = a.x + a.y + a.z + a.w
                      + g_oproj[((size_t)b_a * T_STEPS + t) * 256 + jc];
            g_hidstep[b_a * 256 + jc] = fmaxf(acc, 0.f);
        }
        grid_bar(barv += NCTA);

        // ================= Phase C: o64 = hid @ W2 + b2, sample, write =================
        {
            const int b = c;                  // CTA id = batch row
            float* hbuf = xs;                 // [256]
            float* part = xs + 256;           // [256]
            float* o64  = xs + 512;           // [64]
            if (tid < 64) {
                float4 v = *(const float4*)(g_hidstep + b * 256 + tid * 4);
                *(float4*)(hbuf + tid * 4) = v;
            }
            __syncthreads();
            const int q = tid >> 6, o = tid & 63;
            float acc = 0.f;
#pragma unroll 16
            for (int k = 0; k < 64; k++)
                acc = fmaf(hbuf[q * 64 + k], w2s[(q * 64 + k) * 64 + o], acc);
            part[tid] = acc;
            __syncthreads();
            if (tid < 64) {
                float v = part[tid] + part[64 + tid] + part[128 + tid] + part[192 + tid] + b2s[tid];
                o64[tid] = v;
            }
            __syncthreads();
            if (tid < 32) {
                int s = tid;
                float pm = o64[s];
                float ps = softplusf_(o64[s + 32]) + 0.1f;
                float e  = eps[((size_t)t * B_SZ + b) * 32 + s];
                float z  = fmaf(ps, e, pm);
                size_t base = ((size_t)b * T_STEPS + t) * OUT_D;
                out[base + 352 + s] = pm;
                out[base + 384 + s] = ps;
                out[base + 256 + s] = z;
                g_state[b * 288 + 256 + s] = z;
            }
        }
        grid_bar(barv += NCTA);
    }
}

// ---------------- generic fp32 tiled GEMM: C = act(A@W + bias) ----------------
__global__ void gemm_kernel(int M, int N, int K,
                            const float* __restrict__ A, int lda,
                            const float* __restrict__ W,
                            const float* __restrict__ bias,
                            float* __restrict__ C, int ldc, int act)
{
    __shared__ __align__(16) float As[16][132];
    __shared__ __align__(16) float Ws[16][64];
    const int tid = threadIdx.x;
    const int tx = tid & 15;
    const int ty = tid >> 4;
    const int rowBase = blockIdx.y * 128;
    const int colBase = blockIdx.x * 64;

    float acc[8][4];
#pragma unroll
    for (int i = 0; i < 8; i++)
#pragma unroll
        for (int j = 0; j < 4; j++) acc[i][j] = 0.f;

    const int ka = tid & 15;
    const int ra = tid >> 4;
    const int nw = tid & 63;
    const int kw = tid >> 6;

    for (int k0 = 0; k0 < K; k0 += 16) {
#pragma unroll
        for (int p = 0; p < 8; p++)
            As[ka][ra + p * 16] = A[(size_t)(rowBase + ra + p * 16) * lda + k0 + ka];
#pragma unroll
        for (int p = 0; p < 4; p++)
            Ws[kw + p * 4][nw] = W[(size_t)(k0 + kw + p * 4) * N + colBase + nw];
        __syncthreads();
#pragma unroll
        for (int k = 0; k < 16; k++) {
            float4 av0 = *(const float4*)&As[k][ty * 8];
            float4 av1 = *(const float4*)&As[k][ty * 8 + 4];
            float a[8] = {av0.x, av0.y, av0.z, av0.w, av1.x, av1.y, av1.z, av1.w};
            float4 wv = *(const float4*)&Ws[k][tx * 4];
            float w[4] = {wv.x, wv.y, wv.z, wv.w};
#pragma unroll
            for (int i = 0; i < 8; i++)
#pragma unroll
                for (int j = 0; j < 4; j++) acc[i][j] = fmaf(a[i], w[j], acc[i][j]);
        }
        __syncthreads();
    }
#pragma unroll
    for (int i = 0; i < 8; i++) {
        int r = rowBase + ty * 8 + i;
#pragma unroll
        for (int j = 0; j < 4; j++) {
            int cc = colBase + tx * 4 + j;
            float v = acc[i][j];
            if (bias) v += bias[cc];
            if (act == 1) v = fmaxf(v, 0.f);
            else if (act == 2 && cc >= 32) v = softplusf_(v) + 0.1f;
            C[(size_t)r * ldc + cc] = v;
        }
    }
}

// ---------------- GEMV (N=1): K=256 ----------------
__global__ void gemv_kernel(const float* __restrict__ A, int lda,
                            const float* __restrict__ w,
                            const float* __restrict__ bias, float* __restrict__ C, int act)
{
    const int warp = threadIdx.x >> 5, lane = threadIdx.x & 31;
    const int row = blockIdx.x * 8 + warp;
    const float* a = A + (size_t)row * lda;
    float acc = 0.f;
#pragma unroll
    for (int i = 0; i < 8; i++) acc = fmaf(a[lane + 32 * i], w[lane + 32 * i], acc);
#pragma unroll
    for (int off = 16; off; off >>= 1) acc += __shfl_xor_sync(0xffffffffu, acc, off);
    if (lane == 0) {
        float v = acc + bias[0];
        if (act == 3) v = sigmoidf_(v);
        C[(size_t)row * OUT_D] = v;
    }
}

// ---------------- driver ----------------
extern "C" void kernel_launch(void* const* d_in, const int* in_sizes, int n_in,
                              void* d_out, int out_size)
{
    const float* obs      = (const float*)d_in[0];
    const float* act      = (const float*)d_in[1];
    const float* eps      = (const float*)d_in[2];
    const float* prior_W1 = (const float*)d_in[3];
    const float* prior_b1 = (const float*)d_in[4];
    const float* prior_W2 = (const float*)d_in[5];
    const float* prior_b2 = (const float*)d_in[6];
    const float* post_W1  = (const float*)d_in[7];
    const float* post_b1  = (const float*)d_in[8];
    const float* post_W2  = (const float*)d_in[9];
    const float* post_b2  = (const float*)d_in[10];
    const float* W_ih     = (const float*)d_in[11];
    const float* b_ih     = (const float*)d_in[12];
    const float* W_hh     = (const float*)d_in[13];
    const float* b_hh     = (const float*)d_in[14];
    const float* dobs_W1  = (const float*)d_in[15];
    const float* dobs_b1  = (const float*)d_in[16];
    const float* dobs_W2  = (const float*)d_in[17];
    const float* dobs_b2  = (const float*)d_in[18];
    const float* drew_W1  = (const float*)d_in[19];
    const float* drew_b1  = (const float*)d_in[20];
    const float* drew_W2  = (const float*)d_in[21];
    const float* drew_b2  = (const float*)d_in[22];
    const float* dcont_W1 = (const float*)d_in[23];
    const float* dcont_b1 = (const float*)d_in[24];
    const float* dcont_W2 = (const float*)d_in[25];
    const float* dcont_b2 = (const float*)d_in[26];
    float* out = (float*)d_out;

    float *oproj_p = nullptr, *hid3_p = nullptr, *wcat_p = nullptr, *bcat_p = nullptr;
    cudaGetSymbolAddress((void**)&oproj_p, g_oproj);
    cudaGetSymbolAddress((void**)&hid3_p, g_hid3);
    cudaGetSymbolAddress((void**)&wcat_p, g_Wcat);
    cudaGetSymbolAddress((void**)&bcat_p, g_bcat);

    static int smem_set = 0;
    if (!smem_set) {
        cudaFuncSetAttribute(scan_kernel, cudaFuncAttributeMaxDynamicSharedMemorySize, SMEM_BYTES);
        smem_set = 1;
    }

    prep_kernel<<<1680, 256>>>(W_ih, W_hh);
    prep2_kernel<<<1152, 256>>>(prior_W1, prior_b1, dobs_W1, dobs_b1,
                                drew_W1, drew_b1, dcont_W1, dcont_b1);

    // Phase A: o_proj = obs @ W1o + post_b1  (rows 256..1279 of post_W1)
    gemm_kernel<<<dim3(4, BT / 128), 256>>>(BT, 256, 1024, obs, 1024,
                                            post_W1 + 256 * 256, post_b1,
                                            oproj_p, 256, 0);

    // Phase B: persistent sequential scan (GRU + posterior + sample)
    scan_kernel<<<NCTA, 256, SMEM_BYTES>>>(out, act, eps, b_ih, b_hh,
                                           post_W1, post_W2, post_b2);

    // Phase C: merged decoder/prior L1: hid3 = relu([h,z] @ Wcat + bcat)
    gemm_kernel<<<dim3(16, BT / 128), 256>>>(BT, 1024, 288, out, OUT_D,
                                             wcat_p, bcat_p, hid3_p, 1024, 1);
    // prior L2 (cols 0..255 of hid3)
    gemm_kernel<<<dim3(1, BT / 128), 256>>>(BT, 64, 256, hid3_p, 1024,
                                            prior_W2, prior_b2, out + 288, OUT_D, 2);
    // obs decoder L2 (cols 256..511)
    gemm_kernel<<<dim3(16, BT / 128), 256>>>(BT, 1024, 256, hid3_p + 256, 1024,
                                             dobs_W2, dobs_b2, out + 416, OUT_D, 0);
    // reward (cols 512..767) / continuation (cols 768..1023)
    gemv_kernel<<<BT / 8, 256>>>(hid3_p + 512, 1024, drew_W2, drew_b2, out + 1440, 0);
    gemv_kernel<<<BT / 8, 256>>>(hid3_p + 768, 1024, dcont_W2, dcont_b2, out + 1441, 3);
}

// round 4
// speedup vs baseline: 1.3912x; 1.1244x over previous
#include <cuda_runtime.h>
#include <math.h>

#define T_STEPS 512
#define B_SZ    128
#define BT      (B_SZ * T_STEPS)
#define OUT_D   1442
#define NCTA    128

typedef unsigned long long ull;

// ---------------- scratch (static device globals; no allocation) ----------------
__device__ __align__(16) float g_oproj[BT * 256];          // obs @ W1o + post_b1, [B][T][256]
__device__ __align__(16) float g_hid3 [(size_t)BT * 1024]; // merged decoder hidden
__device__ __align__(16) float g_WihT [768 * 304];         // W_ih transposed: [n][k]
__device__ __align__(16) float g_WhhT [768 * 256];         // W_hh transposed: [n][k]
__device__ __align__(16) float g_Wcat [288 * 1024];        // merged decoder L1 weights
__device__ __align__(16) float g_bcat [1024];
__device__ __align__(16) float g_part [B_SZ * 16 * 64];    // partial o64: [b][jt][64]
__device__ __align__(16) float g_state[B_SZ * 256];        // h only
__device__ unsigned g_cnt;

__device__ __forceinline__ float sigmoidf_(float x) { return 1.f / (1.f + expf(-x)); }
__device__ __forceinline__ float softplusf_(float x) {
    return fmaxf(x, 0.f) + log1pf(expf(-fabsf(x)));
}

// packed fp32x2 helpers (exact fp32 math, 2 FMAs per issue)
__device__ __forceinline__ void fma2(ull& d, ull a, ull b) {
    asm("fma.rn.f32x2 %0, %1, %2, %0;" : "+l"(d) : "l"(a), "l"(b));
}
__device__ __forceinline__ void add2(ull& d, ull a) {
    asm("add.rn.f32x2 %0, %0, %1;" : "+l"(d) : "l"(a));
}
__device__ __forceinline__ ull pack2(float lo, float hi) {
    ull r; asm("mov.b64 %0, {%1, %2};" : "=l"(r) : "f"(lo), "f"(hi)); return r;
}
__device__ __forceinline__ float2 unpack2(ull v) {
    float2 f; asm("mov.b64 {%0, %1}, %2;" : "=f"(f.x), "=f"(f.y) : "l"(v)); return f;
}

// ---------------- prep: transpose GRU weights, reset barrier ----------------
__global__ void prep_kernel(const float* __restrict__ W_ih, const float* __restrict__ W_hh) {
    if (blockIdx.x == 0 && threadIdx.x == 0) g_cnt = 0u;
    int idx = blockIdx.x * 256 + threadIdx.x;
    const int n1 = 768 * 304;
    if (idx < n1) {
        int n = idx / 304, k = idx - n * 304;
        g_WihT[idx] = W_ih[k * 768 + n];
    } else {
        int r = idx - n1;            // exact grid: r < 768*256
        int n = r >> 8, k = r & 255;
        g_WhhT[r] = W_hh[k * 768 + n];
    }
}

// build Wcat[288][1024]
__global__ void prep2_kernel(const float* __restrict__ prior_W1, const float* __restrict__ prior_b1,
                             const float* __restrict__ dobs_W1,  const float* __restrict__ dobs_b1,
                             const float* __restrict__ drew_W1,  const float* __restrict__ drew_b1,
                             const float* __restrict__ dcont_W1, const float* __restrict__ dcont_b1)
{
    int idx = blockIdx.x * 256 + threadIdx.x;      // 288*1024 grid
    int k = idx >> 10, j = idx & 1023;
    int g = j >> 8, jj = j & 255;
    float v;
    if (g == 0)      v = (k < 256) ? prior_W1[k * 256 + jj] : 0.f;
    else if (g == 1) v = dobs_W1[(size_t)k * 256 + jj];
    else if (g == 2) v = drew_W1[(size_t)k * 256 + jj];
    else             v = dcont_W1[(size_t)k * 256 + jj];
    g_Wcat[idx] = v;
    if (idx < 1024) {
        float b;
        if (g == 0)      b = prior_b1[jj];
        else if (g == 1) b = dobs_b1[jj];
        else if (g == 2) b = drew_b1[jj];
        else             b = dcont_b1[jj];
        g_bcat[idx] = b;
    }
}

// ---------------- fast grid barrier: monotonic counter, plain-load poll ----------------
__device__ __forceinline__ void grid_bar(unsigned target) {
    __syncthreads();
    if (threadIdx.x == 0) {
        __threadfence();
        atomicAdd(&g_cnt, 1u);
        volatile unsigned* p = &g_cnt;
        unsigned v;
        do { v = *p; } while (v < target);
        __threadfence();
    }
    __syncthreads();
}

// ---------------- persistent scan kernel ----------------
// 128 CTAs x 256 threads. CTA c: jt = c & 15 (16 h-cols), bt = c >> 4 (16 batch rows).
#define SM_WGRU 0
#define SM_W1H  26880
#define SM_W2   (SM_W1H + 16*260)           // 31040
#define SM_B2   (SM_W2 + 16384)             // 47424
#define SM_XS   (SM_B2 + 64)                // 47488  (xs: 16 x 308)
#define SM_HST  (SM_XS + 16*308)            // 52416  (hstage/hidl: 16 x 17)
#define SM_O64  (SM_HST + 16*17)            // 52688  (o64s: 16 x 64)
#define SM_FLOATS (SM_O64 + 1024)           // 53712
#define SMEM_BYTES (SM_FLOATS * 4)          // 214848

__global__ void __launch_bounds__(256, 1) scan_kernel(
    float* __restrict__ out, const float* __restrict__ act_seq,
    const float* __restrict__ eps,
    const float* __restrict__ b_ih, const float* __restrict__ b_hh,
    const float* __restrict__ post_W1, const float* __restrict__ post_W2,
    const float* __restrict__ post_b2)
{
    extern __shared__ float sm[];
    float* wgru = sm + SM_WGRU;
    float* w1hs = sm + SM_W1H;   // [jl][k] stride 260
    float* w2s  = sm + SM_W2;    // [k][o] 256x64
    float* b2s  = sm + SM_B2;
    float* xs   = sm + SM_XS;    // [16][308]: h(256) z(32) a(16); also reused as hs [16][260]
    float* hst  = sm + SM_HST;   // [16][17]: hstage / hidl
    float* o64s = sm + SM_O64;   // [16][64]

    const int tid = threadIdx.x;
    const int c   = blockIdx.x;
    const int jt  = c & 15;
    const int bt  = c >> 4;
    const int jl  = tid >> 4;
    const int bl  = tid & 15;
    const int jc  = jt * 16 + jl;

    // ---- preload weights into SMEM (once) ----
    for (int idx = tid; idx < 16 * 1680; idx += 256) {
        int j_ = idx / 1680, r = idx - j_ * 1680;
        int j = jt * 16 + j_;
        float v;
        if (r < 912) { int g = r / 304, k = r - g * 304; v = g_WihT[(size_t)(g * 256 + j) * 304 + k]; }
        else { int r2 = r - 912; int g = r2 >> 8, k = r2 & 255; v = g_WhhT[(size_t)(g * 256 + j) * 256 + k]; }
        wgru[idx] = v;
    }
    for (int idx = tid; idx < 16 * 256; idx += 256) {
        int j_ = idx >> 8, k = idx & 255;
        w1hs[j_ * 260 + k] = post_W1[(size_t)k * 256 + jt * 16 + j_];
    }
    for (int idx = tid; idx < 16384; idx += 256) w2s[idx] = post_W2[idx];
    if (tid < 64) b2s[tid] = post_b2[tid];
    __syncthreads();

    const float bir = b_ih[jc], biz = b_ih[jc + 256], bin_ = b_ih[jc + 512];
    const float bhr = b_hh[jc], bhz = b_hh[jc + 256], bhn = b_hh[jc + 512];

    unsigned barv = 0;

    for (int t = 0; t < T_STEPS; t++) {
        // ========== Phase A: reduce partials(t-1) -> z_{t-1}; GRU -> h_t ==========
        if (t == 0) {
            // h_0 = 0
            int b_l = tid >> 4, j_l = tid & 15;
            g_state[(bt * 16 + b_l) * 256 + jt * 16 + j_l] = 0.f;
            out[((size_t)(bt * 16 + b_l) * T_STEPS + 0) * OUT_D + jt * 16 + j_l] = 0.f;
        } else {
            // --- 1) o64 reduction for step t-1 ---
            {
                int b_l = tid >> 4, og = (tid & 15) * 4;
                const float4* bp = (const float4*)(b2s + og);
                float4 racc = *bp;
#pragma unroll
                for (int q = 0; q < 16; q++) {
                    float4 v = *(const float4*)(g_part + ((size_t)(bt * 16 + b_l) * 16 + q) * 64 + og);
                    racc.x += v.x; racc.y += v.y; racc.z += v.z; racc.w += v.w;
                }
                *(float4*)(o64s + b_l * 64 + og) = racc;
            }
            __syncthreads();
            // --- 2) sample z_{t-1}, fill xs z-slots, jt==0 writes outputs ---
            for (int idx = tid; idx < 512; idx += 256) {
                int b_l = idx >> 5, s = idx & 31;
                int b = bt * 16 + b_l;
                float pm = o64s[b_l * 64 + s];
                float ps = softplusf_(o64s[b_l * 64 + 32 + s]) + 0.1f;
                float e  = eps[((size_t)(t - 1) * B_SZ + b) * 32 + s];
                float z  = fmaf(ps, e, pm);
                xs[b_l * 308 + 256 + s] = z;
                if (jt == 0) {
                    size_t base = ((size_t)b * T_STEPS + (t - 1)) * OUT_D;
                    out[base + 352 + s] = pm;
                    out[base + 384 + s] = ps;
                    out[base + 256 + s] = z;
                }
            }
            // --- 3) fill xs: h from g_state, a from act_seq ---
            for (int idx = tid; idx < 16 * 64; idx += 256) {
                int b_l = idx >> 6, k4 = idx & 63;
                float4 v = *(const float4*)(g_state + (bt * 16 + b_l) * 256 + k4 * 4);
                *(float4*)(xs + b_l * 308 + k4 * 4) = v;
            }
            {
                int b_l = tid >> 4, kk = tid & 15;
                xs[b_l * 308 + 288 + kk] =
                    act_seq[((size_t)(bt * 16 + b_l) * T_STEPS + (t - 1)) * 16 + kk];
            }
            __syncthreads();

            // --- 4) GRU with packed f32x2 FMAs ---
            const ulonglong2* xv  = (const ulonglong2*)(xs + bl * 308);
            const ulonglong2* wir = (const ulonglong2*)(wgru + jl * 1680);
            const ulonglong2* wiz = (const ulonglong2*)(wgru + jl * 1680 + 304);
            const ulonglong2* win = (const ulonglong2*)(wgru + jl * 1680 + 608);
            const ulonglong2* whr = (const ulonglong2*)(wgru + jl * 1680 + 912);
            const ulonglong2* whz = (const ulonglong2*)(wgru + jl * 1680 + 1168);
            const ulonglong2* whn = (const ulonglong2*)(wgru + jl * 1680 + 1424);

            ull air0=0, air1=0, aiz0=0, aiz1=0, ain0=0, ain1=0;
            ull ahr0=0, ahr1=0, ahz0=0, ahz1=0, ahn0=0, ahn1=0;
#pragma unroll 4
            for (int k4 = 0; k4 < 64; k4++) {
                ulonglong2 x2 = xv[k4];
                ulonglong2 w;
                w = wir[k4]; fma2(air0, x2.x, w.x); fma2(air1, x2.y, w.y);
                w = wiz[k4]; fma2(aiz0, x2.x, w.x); fma2(aiz1, x2.y, w.y);
                w = win[k4]; fma2(ain0, x2.x, w.x); fma2(ain1, x2.y, w.y);
                w = whr[k4]; fma2(ahr0, x2.x, w.x); fma2(ahr1, x2.y, w.y);
                w = whz[k4]; fma2(ahz0, x2.x, w.x); fma2(ahz1, x2.y, w.y);
                w = whn[k4]; fma2(ahn0, x2.x, w.x); fma2(ahn1, x2.y, w.y);
            }
#pragma unroll
            for (int k4 = 64; k4 < 76; k4++) {   // z,a feed only input gates
                ulonglong2 x2 = xv[k4];
                ulonglong2 w;
                w = wir[k4]; fma2(air0, x2.x, w.x); fma2(air1, x2.y, w.y);
                w = wiz[k4]; fma2(aiz0, x2.x, w.x); fma2(aiz1, x2.y, w.y);
                w = win[k4]; fma2(ain0, x2.x, w.x); fma2(ain1, x2.y, w.y);
            }
            add2(air0, air1); add2(aiz0, aiz1); add2(ain0, ain1);
            add2(ahr0, ahr1); add2(ahz0, ahz1); add2(ahn0, ahn1);
            float2 fr = unpack2(air0), fz = unpack2(aiz0), fn = unpack2(ain0);
            float2 gr = unpack2(ahr0), gz = unpack2(ahz0), gn = unpack2(ahn0);
            float sir = fr.x + fr.y + bir;
            float siz = fz.x + fz.y + biz;
            float sin_= fn.x + fn.y + bin_;
            float shr = gr.x + gr.y + bhr;
            float shz = gz.x + gz.y + bhz;
            float shn = gn.x + gn.y + bhn;

            float r  = sigmoidf_(sir + shr);
            float zg = sigmoidf_(siz + shz);
            float n  = tanhf(sin_ + r * shn);
            float hprev = xs[bl * 308 + jc];
            float hnew  = (1.f - zg) * n + zg * hprev;
            hst[bl * 17 + jl] = hnew;
            __syncthreads();
            // coalesced h writes
            {
                int b_l = tid >> 4, j_l = tid & 15;
                float hv = hst[b_l * 17 + j_l];
                g_state[(bt * 16 + b_l) * 256 + jt * 16 + j_l] = hv;
                out[((size_t)(bt * 16 + b_l) * T_STEPS + t) * OUT_D + jt * 16 + j_l] = hv;
            }
        }
        grid_bar(barv += NCTA);

        // ========== Phase BC: hid slice + partial o64 ==========
        {
            float* hs = xs;   // [16][260]
            for (int idx = tid; idx < 16 * 64; idx += 256) {
                int b_l = idx >> 6, k4 = idx & 63;
                float4 v = *(const float4*)(g_state + (bt * 16 + b_l) * 256 + k4 * 4);
                *(float4*)(hs + b_l * 260 + k4 * 4) = v;
            }
            __syncthreads();
            const ulonglong2* hv2 = (const ulonglong2*)(hs + bl * 260);
            const ulonglong2* wv2 = (const ulonglong2*)(w1hs + jl * 260);
            ull a0 = 0, a1 = 0;
#pragma unroll 8
            for (int k4 = 0; k4 < 64; k4++) {
                ulonglong2 h2 = hv2[k4], w2v = wv2[k4];
                fma2(a0, h2.x, w2v.x);
                fma2(a1, h2.y, w2v.y);
            }
            add2(a0, a1);
            float2 f = unpack2(a0);
            int b = bt * 16 + bl;
            float acc = f.x + f.y + g_oproj[((size_t)b * T_STEPS + t) * 256 + jc];
            hst[bl * 17 + jl] = fmaxf(acc, 0.f);   // hidl
            __syncthreads();
            // partial o64: rank-16 update with W2 rows [jt*16, jt*16+16)
            const int o = tid & 63, bq = tid >> 6;
#pragma unroll
            for (int bb = 0; bb < 4; bb++) {
                int b_l = bq * 4 + bb;
                float pacc = 0.f;
#pragma unroll
                for (int k = 0; k < 16; k++)
                    pacc = fmaf(hst[b_l * 17 + k], w2s[(jt * 16 + k) * 64 + o], pacc);
                g_part[((size_t)(bt * 16 + b_l) * 16 + jt) * 64 + o] = pacc;
            }
        }
        grid_bar(barv += NCTA);
    }

    // ========== epilogue: reduce partials for t=511, write outputs ==========
    {
        const int b = c;                       // one batch row per CTA
        if (tid < 64) {
            float acc = b2s[tid];
#pragma unroll
            for (int q = 0; q < 16; q++)
                acc += g_part[((size_t)b * 16 + q) * 64 + tid];
            o64s[tid] = acc;
        }
        __syncthreads();
        if (tid < 32) {
            int s = tid;
            float pm = o64s[s];
            float ps = softplusf_(o64s[32 + s]) + 0.1f;
            float e  = eps[((size_t)(T_STEPS - 1) * B_SZ + b) * 32 + s];
            float z  = fmaf(ps, e, pm);
            size_t base = ((size_t)b * T_STEPS + (T_STEPS - 1)) * OUT_D;
            out[base + 352 + s] = pm;
            out[base + 384 + s] = ps;
            out[base + 256 + s] = z;
        }
    }
}

// ---------------- fp32 tiled GEMM with f32x2: C = act(A@W + bias) ----------------
__global__ void gemm_kernel(int M, int N, int K,
                            const float* __restrict__ A, int lda,
                            const float* __restrict__ W,
                            const float* __restrict__ bias,
                            float* __restrict__ C, int ldc, int act)
{
    __shared__ __align__(16) float As[16][132];
    __shared__ __align__(16) float Ws[16][64];
    const int tid = threadIdx.x;
    const int tx = tid & 15;
    const int ty = tid >> 4;
    const int rowBase = blockIdx.y * 128;
    const int colBase = blockIdx.x * 64;

    ull acc2[4][4];
#pragma unroll
    for (int p = 0; p < 4; p++)
#pragma unroll
        for (int j = 0; j < 4; j++) acc2[p][j] = 0ull;

    const int ka = tid & 15;
    const int ra = tid >> 4;
    const int nw = tid & 63;
    const int kw = tid >> 6;

    for (int k0 = 0; k0 < K; k0 += 16) {
#pragma unroll
        for (int p = 0; p < 8; p++)
            As[ka][ra + p * 16] = A[(size_t)(rowBase + ra + p * 16) * lda + k0 + ka];
#pragma unroll
        for (int p = 0; p < 4; p++)
            Ws[kw + p * 4][nw] = W[(size_t)(k0 + kw + p * 4) * N + colBase + nw];
        __syncthreads();
#pragma unroll
        for (int k = 0; k < 16; k++) {
            ulonglong2 A01 = *(const ulonglong2*)&As[k][ty * 8];      // rows (0,1),(2,3)
            ulonglong2 A23 = *(const ulonglong2*)&As[k][ty * 8 + 4];  // rows (4,5),(6,7)
            float4 wv = *(const float4*)&Ws[k][tx * 4];
            ull wd0 = pack2(wv.x, wv.x), wd1 = pack2(wv.y, wv.y);
            ull wd2 = pack2(wv.z, wv.z), wd3 = pack2(wv.w, wv.w);
            fma2(acc2[0][0], A01.x, wd0); fma2(acc2[0][1], A01.x, wd1);
            fma2(acc2[0][2], A01.x, wd2); fma2(acc2[0][3], A01.x, wd3);
            fma2(acc2[1][0], A01.y, wd0); fma2(acc2[1][1], A01.y, wd1);
            fma2(acc2[1][2], A01.y, wd2); fma2(acc2[1][3], A01.y, wd3);
            fma2(acc2[2][0], A23.x, wd0); fma2(acc2[2][1], A23.x, wd1);
            fma2(acc2[2][2], A23.x, wd2); fma2(acc2[2][3], A23.x, wd3);
            fma2(acc2[3][0], A23.y, wd0); fma2(acc2[3][1], A23.y, wd1);
            fma2(acc2[3][2], A23.y, wd2); fma2(acc2[3][3], A23.y, wd3);
        }
        __syncthreads();
    }
#pragma unroll
    for (int p = 0; p < 4; p++) {
#pragma unroll
        for (int j = 0; j < 4; j++) {
            float2 f = unpack2(acc2[p][j]);
            int cc = colBase + tx * 4 + j;
            float bval = bias ? bias[cc] : 0.f;
            float v0 = f.x + bval;
            float v1 = f.y + bval;
            if (act == 1) { v0 = fmaxf(v0, 0.f); v1 = fmaxf(v1, 0.f); }
            else if (act == 2 && cc >= 32) {
                v0 = softplusf_(v0) + 0.1f;
                v1 = softplusf_(v1) + 0.1f;
            }
            int r0 = rowBase + ty * 8 + 2 * p;
            C[(size_t)r0 * ldc + cc] = v0;
            C[(size_t)(r0 + 1) * ldc + cc] = v1;
        }
    }
}

// ---------------- GEMV (N=1): K=256 ----------------
__global__ void gemv_kernel(const float* __restrict__ A, int lda,
                            const float* __restrict__ w,
                            const float* __restrict__ bias, float* __restrict__ C, int act)
{
    const int warp = threadIdx.x >> 5, lane = threadIdx.x & 31;
    const int row = blockIdx.x * 8 + warp;
    const float* a = A + (size_t)row * lda;
    float acc = 0.f;
#pragma unroll
    for (int i = 0; i < 8; i++) acc = fmaf(a[lane + 32 * i], w[lane + 32 * i], acc);
#pragma unroll
    for (int off = 16; off; off >>= 1) acc += __shfl_xor_sync(0xffffffffu, acc, off);
    if (lane == 0) {
        float v = acc + bias[0];
        if (act == 3) v = sigmoidf_(v);
        C[(size_t)row * OUT_D] = v;
    }
}

// ---------------- driver ----------------
extern "C" void kernel_launch(void* const* d_in, const int* in_sizes, int n_in,
                              void* d_out, int out_size)
{
    const float* obs      = (const float*)d_in[0];
    const float* act      = (const float*)d_in[1];
    const float* eps      = (const float*)d_in[2];
    const float* prior_W1 = (const float*)d_in[3];
    const float* prior_b1 = (const float*)d_in[4];
    const float* prior_W2 = (const float*)d_in[5];
    const float* prior_b2 = (const float*)d_in[6];
    const float* post_W1  = (const float*)d_in[7];
    const float* post_b1  = (const float*)d_in[8];
    const float* post_W2  = (const float*)d_in[9];
    const float* post_b2  = (const float*)d_in[10];
    const float* W_ih     = (const float*)d_in[11];
    const float* b_ih     = (const float*)d_in[12];
    const float* W_hh     = (const float*)d_in[13];
    const float* b_hh     = (const float*)d_in[14];
    const float* dobs_W1  = (const float*)d_in[15];
    const float* dobs_b1  = (const float*)d_in[16];
    const float* dobs_W2  = (const float*)d_in[17];
    const float* dobs_b2  = (const float*)d_in[18];
    const float* drew_W1  = (const float*)d_in[19];
    const float* drew_b1  = (const float*)d_in[20];
    const float* drew_W2  = (const float*)d_in[21];
    const float* drew_b2  = (const float*)d_in[22];
    const float* dcont_W1 = (const float*)d_in[23];
    const float* dcont_b1 = (const float*)d_in[24];
    const float* dcont_W2 = (const float*)d_in[25];
    const float* dcont_b2 = (const float*)d_in[26];
    float* out = (float*)d_out;

    float *oproj_p = nullptr, *hid3_p = nullptr, *wcat_p = nullptr, *bcat_p = nullptr;
    cudaGetSymbolAddress((void**)&oproj_p, g_oproj);
    cudaGetSymbolAddress((void**)&hid3_p, g_hid3);
    cudaGetSymbolAddress((void**)&wcat_p, g_Wcat);
    cudaGetSymbolAddress((void**)&bcat_p, g_bcat);

    static int smem_set = 0;
    if (!smem_set) {
        cudaFuncSetAttribute(scan_kernel, cudaFuncAttributeMaxDynamicSharedMemorySize, SMEM_BYTES);
        smem_set = 1;
    }

    prep_kernel<<<1680, 256>>>(W_ih, W_hh);
    prep2_kernel<<<1152, 256>>>(prior_W1, prior_b1, dobs_W1, dobs_b1,
                                drew_W1, drew_b1, dcont_W1, dcont_b1);

    // Phase A: o_proj = obs @ W1o + post_b1  (rows 256..1279 of post_W1)
    gemm_kernel<<<dim3(4, BT / 128), 256>>>(BT, 256, 1024, obs, 1024,
                                            post_W1 + 256 * 256, post_b1,
                                            oproj_p, 256, 0);

    // Phase B: persistent sequential scan (GRU + posterior + sample)
    scan_kernel<<<NCTA, 256, SMEM_BYTES>>>(out, act, eps, b_ih, b_hh,
                                           post_W1, post_W2, post_b2);

    // Phase C: merged decoder/prior L1: hid3 = relu([h,z] @ Wcat + bcat)
    gemm_kernel<<<dim3(16, BT / 128), 256>>>(BT, 1024, 288, out, OUT_D,
                                             wcat_p, bcat_p, hid3_p, 1024, 1);
    // prior L2 (cols 0..255 of hid3)
    gemm_kernel<<<dim3(1, BT / 128), 256>>>(BT, 64, 256, hid3_p, 1024,
                                            prior_W2, prior_b2, out + 288, OUT_D, 2);
    // obs decoder L2 (cols 256..511)
    gemm_kernel<<<dim3(16, BT / 128), 256>>>(BT, 1024, 256, hid3_p + 256, 1024,
                                             dobs_W2, dobs_b2, out + 416, OUT_D, 0);
    // reward (cols 512..767) / continuation (cols 768..1023)
    gemv_kernel<<<BT / 8, 256>>>(hid3_p + 512, 1024, drew_W2, drew_b2, out + 1440, 0);
    gemv_kernel<<<BT / 8, 256>>>(hid3_p + 768, 1024, dcont_W2, dcont_b2, out + 1441, 3);
}

// round 5
// speedup vs baseline: 1.4072x; 1.0114x over previous
#include <cuda_runtime.h>
#include <math.h>

#define T_STEPS 512
#define B_SZ    128
#define BT      (B_SZ * T_STEPS)
#define OUT_D   1442
#define NCTA    128

typedef unsigned long long ull;

// ---------------- scratch (static device globals; no allocation) ----------------
__device__ __align__(16) float g_oproj[BT * 256];          // obs @ W1o + post_b1, [B][T][256]
__device__ __align__(16) float g_hid3 [(size_t)BT * 1024]; // merged decoder hidden
__device__ __align__(16) float g_WihT [768 * 304];         // W_ih transposed: [n][k]
__device__ __align__(16) float g_WhhT [768 * 256];         // W_hh transposed: [n][k]
__device__ __align__(16) float g_Wcat [288 * 1024];        // merged decoder L1 weights
__device__ __align__(16) float g_bcat [1024];
__device__ __align__(16) float g_part [B_SZ * 16 * 64];    // partial o64: [b][jt][64]
__device__ __align__(16) float g_state[B_SZ * 256];        // h only
__device__ unsigned g_cnts[8 * 32];                        // per-group barrier counters (128B apart)

__device__ __forceinline__ float sigmoidf_(float x) { return 1.f / (1.f + expf(-x)); }
__device__ __forceinline__ float softplusf_(float x) {
    return fmaxf(x, 0.f) + log1pf(expf(-fabsf(x)));
}

// packed fp32x2 helpers (exact fp32 math, 2 FMAs per issue)
__device__ __forceinline__ void fma2(ull& d, ull a, ull b) {
    asm("fma.rn.f32x2 %0, %1, %2, %0;" : "+l"(d) : "l"(a), "l"(b));
}
__device__ __forceinline__ void add2(ull& d, ull a) {
    asm("add.rn.f32x2 %0, %0, %1;" : "+l"(d) : "l"(a));
}
__device__ __forceinline__ ull pack2(float lo, float hi) {
    ull r; asm("mov.b64 %0, {%1, %2};" : "=l"(r) : "f"(lo), "f"(hi)); return r;
}
__device__ __forceinline__ float2 unpack2(ull v) {
    float2 f; asm("mov.b64 {%0, %1}, %2;" : "=f"(f.x), "=f"(f.y) : "l"(v)); return f;
}

// ---------------- prep: transpose GRU weights, reset barriers ----------------
__global__ void prep_kernel(const float* __restrict__ W_ih, const float* __restrict__ W_hh) {
    if (blockIdx.x == 0 && threadIdx.x < 8) g_cnts[threadIdx.x * 32] = 0u;
    int idx = blockIdx.x * 256 + threadIdx.x;
    const int n1 = 768 * 304;
    if (idx < n1) {
        int n = idx / 304, k = idx - n * 304;
        g_WihT[idx] = W_ih[k * 768 + n];
    } else {
        int r = idx - n1;            // exact grid: r < 768*256
        int n = r >> 8, k = r & 255;
        g_WhhT[r] = W_hh[k * 768 + n];
    }
}

// build Wcat[288][1024]
__global__ void prep2_kernel(const float* __restrict__ prior_W1, const float* __restrict__ prior_b1,
                             const float* __restrict__ dobs_W1,  const float* __restrict__ dobs_b1,
                             const float* __restrict__ drew_W1,  const float* __restrict__ drew_b1,
                             const float* __restrict__ dcont_W1, const float* __restrict__ dcont_b1)
{
    int idx = blockIdx.x * 256 + threadIdx.x;      // 288*1024 grid
    int k = idx >> 10, j = idx & 1023;
    int g = j >> 8, jj = j & 255;
    float v;
    if (g == 0)      v = (k < 256) ? prior_W1[k * 256 + jj] : 0.f;
    else if (g == 1) v = dobs_W1[(size_t)k * 256 + jj];
    else if (g == 2) v = drew_W1[(size_t)k * 256 + jj];
    else             v = dcont_W1[(size_t)k * 256 + jj];
    g_Wcat[idx] = v;
    if (idx < 1024) {
        float b;
        if (g == 0)      b = prior_b1[jj];
        else if (g == 1) b = dobs_b1[jj];
        else if (g == 2) b = drew_b1[jj];
        else             b = dcont_b1[jj];
        g_bcat[idx] = b;
    }
}

// ---------------- per-group barrier: 16 CTAs, monotonic counter, plain-load poll ----------------
__device__ __forceinline__ void group_bar(unsigned* cnt, unsigned target) {
    __syncthreads();
    if (threadIdx.x == 0) {
        __threadfence();
        atomicAdd(cnt, 1u);
        volatile unsigned* p = cnt;
        unsigned v;
        do { v = *p; } while (v < target);
        __threadfence();
    }
    __syncthreads();
}

// ---------------- persistent scan kernel ----------------
// 128 CTAs x 256 threads. CTA c: jt = c & 15 (16 h-cols), bt = c >> 4 (16 batch rows).
// The 8 bt-groups are fully independent: all sync is within a group.
#define SM_WGRU 0
#define SM_W1H  26880
#define SM_W2   (SM_W1H + 16*260)           // 31040
#define SM_B2   (SM_W2 + 16384)             // 47424
#define SM_XS   (SM_B2 + 64)                // 47488  (xs: 16 x 308)
#define SM_HST  (SM_XS + 16*308)            // 52416  (hstage/hidl: 16 x 17)
#define SM_O64  (SM_HST + 16*17)            // 52688  (o64s: 16 x 64)
#define SM_FLOATS (SM_O64 + 1024)           // 53712
#define SMEM_BYTES (SM_FLOATS * 4)          // 214848

__global__ void __launch_bounds__(256, 1) scan_kernel(
    float* __restrict__ out, const float* __restrict__ act_seq,
    const float* __restrict__ eps,
    const float* __restrict__ b_ih, const float* __restrict__ b_hh,
    const float* __restrict__ post_W1, const float* __restrict__ post_W2,
    const float* __restrict__ post_b2)
{
    extern __shared__ float sm[];
    float* wgru = sm + SM_WGRU;
    float* w1hs = sm + SM_W1H;   // [jl][k] stride 260
    float* w2s  = sm + SM_W2;    // [k][o] 256x64
    float* b2s  = sm + SM_B2;
    float* xs   = sm + SM_XS;    // [16][308]: h(256) z(32) a(16); also reused as hs [16][260]
    float* hst  = sm + SM_HST;   // [16][17]: hstage / hidl
    float* o64s = sm + SM_O64;   // [16][64]

    const int tid = threadIdx.x;
    const int c   = blockIdx.x;
    const int jt  = c & 15;
    const int bt  = c >> 4;
    const int jl  = tid >> 4;
    const int bl  = tid & 15;
    const int jc  = jt * 16 + jl;
    unsigned* cnt = &g_cnts[bt * 32];

    // ---- preload weights into SMEM (once) ----
    for (int idx = tid; idx < 16 * 1680; idx += 256) {
        int j_ = idx / 1680, r = idx - j_ * 1680;
        int j = jt * 16 + j_;
        float v;
        if (r < 912) { int g = r / 304, k = r - g * 304; v = g_WihT[(size_t)(g * 256 + j) * 304 + k]; }
        else { int r2 = r - 912; int g = r2 >> 8, k = r2 & 255; v = g_WhhT[(size_t)(g * 256 + j) * 256 + k]; }
        wgru[idx] = v;
    }
    for (int idx = tid; idx < 16 * 256; idx += 256) {
        int j_ = idx >> 8, k = idx & 255;
        w1hs[j_ * 260 + k] = post_W1[(size_t)k * 256 + jt * 16 + j_];
    }
    for (int idx = tid; idx < 16384; idx += 256) w2s[idx] = post_W2[idx];
    if (tid < 64) b2s[tid] = post_b2[tid];
    __syncthreads();

    const float bir = b_ih[jc], biz = b_ih[jc + 256], bin_ = b_ih[jc + 512];
    const float bhr = b_hh[jc], bhz = b_hh[jc + 256], bhn = b_hh[jc + 512];

    unsigned barv = 0;

    for (int t = 0; t < T_STEPS; t++) {
        // ========== Phase A: reduce partials(t-1) -> z_{t-1}; GRU -> h_t ==========
        if (t == 0) {
            // h_0 = 0
            int b_l = tid >> 4, j_l = tid & 15;
            g_state[(bt * 16 + b_l) * 256 + jt * 16 + j_l] = 0.f;
            out[((size_t)(bt * 16 + b_l) * T_STEPS + 0) * OUT_D + jt * 16 + j_l] = 0.f;
        } else {
            // --- 1) o64 reduction for step t-1 ---
            {
                int b_l = tid >> 4, og = (tid & 15) * 4;
                const float4* bp = (const float4*)(b2s + og);
                float4 racc = *bp;
#pragma unroll
                for (int q = 0; q < 16; q++) {
                    float4 v = *(const float4*)(g_part + ((size_t)(bt * 16 + b_l) * 16 + q) * 64 + og);
                    racc.x += v.x; racc.y += v.y; racc.z += v.z; racc.w += v.w;
                }
                *(float4*)(o64s + b_l * 64 + og) = racc;
            }
            __syncthreads();
            // --- 2) sample z_{t-1}, fill xs z-slots, jt==0 writes outputs ---
            for (int idx = tid; idx < 512; idx += 256) {
                int b_l = idx >> 5, s = idx & 31;
                int b = bt * 16 + b_l;
                float pm = o64s[b_l * 64 + s];
                float ps = softplusf_(o64s[b_l * 64 + 32 + s]) + 0.1f;
                float e  = eps[((size_t)(t - 1) * B_SZ + b) * 32 + s];
                float z  = fmaf(ps, e, pm);
                xs[b_l * 308 + 256 + s] = z;
                if (jt == 0) {
                    size_t base = ((size_t)b * T_STEPS + (t - 1)) * OUT_D;
                    out[base + 352 + s] = pm;
                    out[base + 384 + s] = ps;
                    out[base + 256 + s] = z;
                }
            }
            // --- 3) fill xs: h from g_state, a from act_seq ---
            for (int idx = tid; idx < 16 * 64; idx += 256) {
                int b_l = idx >> 6, k4 = idx & 63;
                float4 v = *(const float4*)(g_state + (bt * 16 + b_l) * 256 + k4 * 4);
                *(float4*)(xs + b_l * 308 + k4 * 4) = v;
            }
            {
                int b_l = tid >> 4, kk = tid & 15;
                xs[b_l * 308 + 288 + kk] =
                    act_seq[((size_t)(bt * 16 + b_l) * T_STEPS + (t - 1)) * 16 + kk];
            }
            __syncthreads();

            // --- 4) GRU with packed f32x2 FMAs ---
            const ulonglong2* xv  = (const ulonglong2*)(xs + bl * 308);
            const ulonglong2* wir = (const ulonglong2*)(wgru + jl * 1680);
            const ulonglong2* wiz = (const ulonglong2*)(wgru + jl * 1680 + 304);
            const ulonglong2* win = (const ulonglong2*)(wgru + jl * 1680 + 608);
            const ulonglong2* whr = (const ulonglong2*)(wgru + jl * 1680 + 912);
            const ulonglong2* whz = (const ulonglong2*)(wgru + jl * 1680 + 1168);
            const ulonglong2* whn = (const ulonglong2*)(wgru + jl * 1680 + 1424);

            ull air0=0, air1=0, aiz0=0, aiz1=0, ain0=0, ain1=0;
            ull ahr0=0, ahr1=0, ahz0=0, ahz1=0, ahn0=0, ahn1=0;
#pragma unroll 4
            for (int k4 = 0; k4 < 64; k4++) {
                ulonglong2 x2 = xv[k4];
                ulonglong2 w;
                w = wir[k4]; fma2(air0, x2.x, w.x); fma2(air1, x2.y, w.y);
                w = wiz[k4]; fma2(aiz0, x2.x, w.x); fma2(aiz1, x2.y, w.y);
                w = win[k4]; fma2(ain0, x2.x, w.x); fma2(ain1, x2.y, w.y);
                w = whr[k4]; fma2(ahr0, x2.x, w.x); fma2(ahr1, x2.y, w.y);
                w = whz[k4]; fma2(ahz0, x2.x, w.x); fma2(ahz1, x2.y, w.y);
                w = whn[k4]; fma2(ahn0, x2.x, w.x); fma2(ahn1, x2.y, w.y);
            }
#pragma unroll
            for (int k4 = 64; k4 < 76; k4++) {   // z,a feed only input gates
                ulonglong2 x2 = xv[k4];
                ulonglong2 w;
                w = wir[k4]; fma2(air0, x2.x, w.x); fma2(air1, x2.y, w.y);
                w = wiz[k4]; fma2(aiz0, x2.x, w.x); fma2(aiz1, x2.y, w.y);
                w = win[k4]; fma2(ain0, x2.x, w.x); fma2(ain1, x2.y, w.y);
            }
            add2(air0, air1); add2(aiz0, aiz1); add2(ain0, ain1);
            add2(ahr0, ahr1); add2(ahz0, ahz1); add2(ahn0, ahn1);
            float2 fr = unpack2(air0), fz = unpack2(aiz0), fn = unpack2(ain0);
            float2 gr = unpack2(ahr0), gz = unpack2(ahz0), gn = unpack2(ahn0);
            float sir = fr.x + fr.y + bir;
            float siz = fz.x + fz.y + biz;
            float sin_= fn.x + fn.y + bin_;
            float shr = gr.x + gr.y + bhr;
            float shz = gz.x + gz.y + bhz;
            float shn = gn.x + gn.y + bhn;

            float r  = sigmoidf_(sir + shr);
            float zg = sigmoidf_(siz + shz);
            float n  = tanhf(sin_ + r * shn);
            float hprev = xs[bl * 308 + jc];
            float hnew  = (1.f - zg) * n + zg * hprev;
            hst[bl * 17 + jl] = hnew;
            __syncthreads();
            // coalesced h writes
            {
                int b_l = tid >> 4, j_l = tid & 15;
                float hv = hst[b_l * 17 + j_l];
                g_state[(bt * 16 + b_l) * 256 + jt * 16 + j_l] = hv;
                out[((size_t)(bt * 16 + b_l) * T_STEPS + t) * OUT_D + jt * 16 + j_l] = hv;
            }
        }
        group_bar(cnt, barv += 16);

        // ========== Phase BC: hid slice + partial o64 ==========
        {
            float* hs = xs;   // [16][260]
            for (int idx = tid; idx < 16 * 64; idx += 256) {
                int b_l = idx >> 6, k4 = idx & 63;
                float4 v = *(const float4*)(g_state + (bt * 16 + b_l) * 256 + k4 * 4);
                *(float4*)(hs + b_l * 260 + k4 * 4) = v;
            }
            __syncthreads();
            const ulonglong2* hv2 = (const ulonglong2*)(hs + bl * 260);
            const ulonglong2* wv2 = (const ulonglong2*)(w1hs + jl * 260);
            ull a0 = 0, a1 = 0;
#pragma unroll 8
            for (int k4 = 0; k4 < 64; k4++) {
                ulonglong2 h2 = hv2[k4], w2v = wv2[k4];
                fma2(a0, h2.x, w2v.x);
                fma2(a1, h2.y, w2v.y);
            }
            add2(a0, a1);
            float2 f = unpack2(a0);
            int b = bt * 16 + bl;
            float acc = f.x + f.y + g_oproj[((size_t)b * T_STEPS + t) * 256 + jc];
            hst[bl * 17 + jl] = fmaxf(acc, 0.f);   // hidl
            __syncthreads();
            // partial o64: rank-16 update with W2 rows [jt*16, jt*16+16)
            const int o = tid & 63, bq = tid >> 6;
#pragma unroll
            for (int bb = 0; bb < 4; bb++) {
                int b_l = bq * 4 + bb;
                float pacc = 0.f;
#pragma unroll
                for (int k = 0; k < 16; k++)
                    pacc = fmaf(hst[b_l * 17 + k], w2s[(jt * 16 + k) * 64 + o], pacc);
                g_part[((size_t)(bt * 16 + b_l) * 16 + jt) * 64 + o] = pacc;
            }
        }
        group_bar(cnt, barv += 16);
    }

    // ========== epilogue: reduce partials for t=511, write outputs ==========
    {
        const int b = c;                       // one batch row per CTA (same bt-group)
        if (tid < 64) {
            float acc = b2s[tid];
#pragma unroll
            for (int q = 0; q < 16; q++)
                acc += g_part[((size_t)b * 16 + q) * 64 + tid];
            o64s[tid] = acc;
        }
        __syncthreads();
        if (tid < 32) {
            int s = tid;
            float pm = o64s[s];
            float ps = softplusf_(o64s[32 + s]) + 0.1f;
            float e  = eps[((size_t)(T_STEPS - 1) * B_SZ + b) * 32 + s];
            float z  = fmaf(ps, e, pm);
            size_t base = ((size_t)b * T_STEPS + (T_STEPS - 1)) * OUT_D;
            out[base + 352 + s] = pm;
            out[base + 384 + s] = ps;
            out[base + 256 + s] = z;
        }
    }
}

// ---------------- fp32 tiled GEMM with f32x2: C = act(A@W + bias) ----------------
__global__ void gemm_kernel(int M, int N, int K,
                            const float* __restrict__ A, int lda,
                            const float* __restrict__ W,
                            const float* __restrict__ bias,
                            float* __restrict__ C, int ldc, int act)
{
    __shared__ __align__(16) float As[16][132];
    __shared__ __align__(16) float Ws[16][64];
    const int tid = threadIdx.x;
    const int tx = tid & 15;
    const int ty = tid >> 4;
    const int rowBase = blockIdx.y * 128;
    const int colBase = blockIdx.x * 64;

    ull acc2[4][4];
#pragma unroll
    for (int p = 0; p < 4; p++)
#pragma unroll
        for (int j = 0; j < 4; j++) acc2[p][j] = 0ull;

    const int ka = tid & 15;
    const int ra = tid >> 4;
    const int nw = tid & 63;
    const int kw = tid >> 6;

    for (int k0 = 0; k0 < K; k0 += 16) {
#pragma unroll
        for (int p = 0; p < 8; p++)
            As[ka][ra + p * 16] = A[(size_t)(rowBase + ra + p * 16) * lda + k0 + ka];
#pragma unroll
        for (int p = 0; p < 4; p++)
            Ws[kw + p * 4][nw] = W[(size_t)(k0 + kw + p * 4) * N + colBase + nw];
        __syncthreads();
#pragma unroll
        for (int k = 0; k < 16; k++) {
            ulonglong2 A01 = *(const ulonglong2*)&As[k][ty * 8];      // rows (0,1),(2,3)
            ulonglong2 A23 = *(const ulonglong2*)&As[k][ty * 8 + 4];  // rows (4,5),(6,7)
            float4 wv = *(const float4*)&Ws[k][tx * 4];
            ull wd0 = pack2(wv.x, wv.x), wd1 = pack2(wv.y, wv.y);
            ull wd2 = pack2(wv.z, wv.z), wd3 = pack2(wv.w, wv.w);
            fma2(acc2[0][0], A01.x, wd0); fma2(acc2[0][1], A01.x, wd1);
            fma2(acc2[0][2], A01.x, wd2); fma2(acc2[0][3], A01.x, wd3);
            fma2(acc2[1][0], A01.y, wd0); fma2(acc2[1][1], A01.y, wd1);
            fma2(acc2[1][2], A01.y, wd2); fma2(acc2[1][3], A01.y, wd3);
            fma2(acc2[2][0], A23.x, wd0); fma2(acc2[2][1], A23.x, wd1);
            fma2(acc2[2][2], A23.x, wd2); fma2(acc2[2][3], A23.x, wd3);
            fma2(acc2[3][0], A23.y, wd0); fma2(acc2[3][1], A23.y, wd1);
            fma2(acc2[3][2], A23.y, wd2); fma2(acc2[3][3], A23.y, wd3);
        }
        __syncthreads();
    }
#pragma unroll
    for (int p = 0; p < 4; p++) {
#pragma unroll
        for (int j = 0; j < 4; j++) {
            float2 f = unpack2(acc2[p][j]);
            int cc = colBase + tx * 4 + j;
            float bval = bias ? bias[cc] : 0.f;
            float v0 = f.x + bval;
            float v1 = f.y + bval;
            if (act == 1) { v0 = fmaxf(v0, 0.f); v1 = fmaxf(v1, 0.f); }
            else if (act == 2 && cc >= 32) {
                v0 = softplusf_(v0) + 0.1f;
                v1 = softplusf_(v1) + 0.1f;
            }
            int r0 = rowBase + ty * 8 + 2 * p;
            C[(size_t)r0 * ldc + cc] = v0;
            C[(size_t)(r0 + 1) * ldc + cc] = v1;
        }
    }
}

// ---------------- GEMV (N=1): K=256 ----------------
__global__ void gemv_kernel(const float* __restrict__ A, int lda,
                            const float* __restrict__ w,
                            const float* __restrict__ bias, float* __restrict__ C, int act)
{
    const int warp = threadIdx.x >> 5, lane = threadIdx.x & 31;
    const int row = blockIdx.x * 8 + warp;
    const float* a = A + (size_t)row * lda;
    float acc = 0.f;
#pragma unroll
    for (int i = 0; i < 8; i++) acc = fmaf(a[lane + 32 * i], w[lane + 32 * i], acc);
#pragma unroll
    for (int off = 16; off; off >>= 1) acc += __shfl_xor_sync(0xffffffffu, acc, off);
    if (lane == 0) {
        float v = acc + bias[0];
        if (act == 3) v = sigmoidf_(v);
        C[(size_t)row * OUT_D] = v;
    }
}

// ---------------- driver ----------------
extern "C" void kernel_launch(void* const* d_in, const int* in_sizes, int n_in,
                              void* d_out, int out_size)
{
    const float* obs      = (const float*)d_in[0];
    const float* act      = (const float*)d_in[1];
    const float* eps      = (const float*)d_in[2];
    const float* prior_W1 = (const float*)d_in[3];
    const float* prior_b1 = (const float*)d_in[4];
    const float* prior_W2 = (const float*)d_in[5];
    const float* prior_b2 = (const float*)d_in[6];
    const float* post_W1  = (const float*)d_in[7];
    const float* post_b1  = (const float*)d_in[8];
    const float* post_W2  = (const float*)d_in[9];
    const float* post_b2  = (const float*)d_in[10];
    const float* W_ih     = (const float*)d_in[11];
    const float* b_ih     = (const float*)d_in[12];
    const float* W_hh     = (const float*)d_in[13];
    const float* b_hh     = (const float*)d_in[14];
    const float* dobs_W1  = (const float*)d_in[15];
    const float* dobs_b1  = (const float*)d_in[16];
    const float* dobs_W2  = (const float*)d_in[17];
    const float* dobs_b2  = (const float*)d_in[18];
    const float* drew_W1  = (const float*)d_in[19];
    const float* drew_b1  = (const float*)d_in[20];
    const float* drew_W2  = (const float*)d_in[21];
    const float* drew_b2  = (const float*)d_in[22];
    const float* dcont_W1 = (const float*)d_in[23];
    const float* dcont_b1 = (const float*)d_in[24];
    const float* dcont_W2 = (const float*)d_in[25];
    const float* dcont_b2 = (const float*)d_in[26];
    float* out = (float*)d_out;

    float *oproj_p = nullptr, *hid3_p = nullptr, *wcat_p = nullptr, *bcat_p = nullptr;
    cudaGetSymbolAddress((void**)&oproj_p, g_oproj);
    cudaGetSymbolAddress((void**)&hid3_p, g_hid3);
    cudaGetSymbolAddress((void**)&wcat_p, g_Wcat);
    cudaGetSymbolAddress((void**)&bcat_p, g_bcat);

    static int smem_set = 0;
    if (!smem_set) {
        cudaFuncSetAttribute(scan_kernel, cudaFuncAttributeMaxDynamicSharedMemorySize, SMEM_BYTES);
        smem_set = 1;
    }

    prep_kernel<<<1680, 256>>>(W_ih, W_hh);
    prep2_kernel<<<1152, 256>>>(prior_W1, prior_b1, dobs_W1, dobs_b1,
                                drew_W1, drew_b1, dcont_W1, dcont_b1);

    // Phase A: o_proj = obs @ W1o + post_b1  (rows 256..1279 of post_W1)
    gemm_kernel<<<dim3(4, BT / 128), 256>>>(BT, 256, 1024, obs, 1024,
                                            post_W1 + 256 * 256, post_b1,
                                            oproj_p, 256, 0);

    // Phase B: persistent sequential scan (GRU + posterior + sample)
    scan_kernel<<<NCTA, 256, SMEM_BYTES>>>(out, act, eps, b_ih, b_hh,
                                           post_W1, post_W2, post_b2);

    // Phase C: merged decoder/prior L1: hid3 = relu([h,z] @ Wcat + bcat)
    gemm_kernel<<<dim3(16, BT / 128), 256>>>(BT, 1024, 288, out, OUT_D,
                                             wcat_p, bcat_p, hid3_p, 1024, 1);
    // prior L2 (cols 0..255 of hid3)
    gemm_kernel<<<dim3(1, BT / 128), 256>>>(BT, 64, 256, hid3_p, 1024,
                                            prior_W2, prior_b2, out + 288, OUT_D, 2);
    // obs decoder L2 (cols 256..511)
    gemm_kernel<<<dim3(16, BT / 128), 256>>>(BT, 1024, 256, hid3_p + 256, 1024,
                                             dobs_W2, dobs_b2, out + 416, OUT_D, 0);
    // reward (cols 512..767) / continuation (cols 768..1023)
    gemv_kernel<<<BT / 8, 256>>>(hid3_p + 512, 1024, drew_W2, drew_b2, out + 1440, 0);
    gemv_kernel<<<BT / 8, 256>>>(hid3_p + 768, 1024, dcont_W2, dcont_b2, out + 1441, 3);
}

// round 6
// speedup vs baseline: 1.6488x; 1.1717x over previous
#include <cuda_runtime.h>
#include <math.h>

#define T_STEPS 512
#define B_SZ    128
#define BT      (B_SZ * T_STEPS)
#define OUT_D   1442
#define NCTA    128

typedef unsigned long long ull;

// ---------------- scratch (static device globals; no allocation) ----------------
__device__ __align__(16) float g_oproj[BT * 256];          // obs @ W1o + post_b1, [B][T][256]
__device__ __align__(16) float g_hid3 [(size_t)BT * 1024]; // merged decoder hidden
__device__ __align__(16) float g_WihT [768 * 304];         // W_ih transposed: [n][k]
__device__ __align__(16) float g_WhhT [768 * 256];         // W_hh transposed: [n][k]
__device__ __align__(16) float g_Wcat [288 * 1024];        // merged decoder L1 weights
__device__ __align__(16) float g_bcat [1024];
__device__ __align__(16) float g_part [B_SZ * 16 * 64];    // partial o64: [b][jt][64]
__device__ __align__(16) float g_state[B_SZ * 256];        // h only
__device__ unsigned g_cnts[8 * 32];                        // per-group barrier counters (128B apart)

__device__ __forceinline__ float sigmoidf_(float x) { return 1.f / (1.f + expf(-x)); }
__device__ __forceinline__ float softplusf_(float x) {
    return fmaxf(x, 0.f) + log1pf(expf(-fabsf(x)));
}

// packed fp32x2 helpers (exact fp32 math, 2 FMAs per issue)
__device__ __forceinline__ void fma2(ull& d, ull a, ull b) {
    asm("fma.rn.f32x2 %0, %1, %2, %0;" : "+l"(d) : "l"(a), "l"(b));
}
__device__ __forceinline__ void add2(ull& d, ull a) {
    asm("add.rn.f32x2 %0, %0, %1;" : "+l"(d) : "l"(a));
}
__device__ __forceinline__ ull pack2(float lo, float hi) {
    ull r; asm("mov.b64 %0, {%1, %2};" : "=l"(r) : "f"(lo), "f"(hi)); return r;
}
__device__ __forceinline__ float2 unpack2(ull v) {
    float2 f; asm("mov.b64 {%0, %1}, %2;" : "=f"(f.x), "=f"(f.y) : "l"(v)); return f;
}

// L2-direct loads (bypass L1 -> always fresh after acquire)
__device__ __forceinline__ float4 ldcg4(const float* p) {
    float4 v;
    asm volatile("ld.global.cg.v4.f32 {%0,%1,%2,%3}, [%4];"
                 : "=f"(v.x), "=f"(v.y), "=f"(v.z), "=f"(v.w) : "l"(p));
    return v;
}
__device__ __forceinline__ float ldcg1(const float* p) {
    float v;
    asm volatile("ld.global.cg.f32 %0, [%1];" : "=f"(v) : "l"(p));
    return v;
}

// ---------------- prep: transpose GRU weights, reset barriers ----------------
__global__ void prep_kernel(const float* __restrict__ W_ih, const float* __restrict__ W_hh) {
    if (blockIdx.x == 0 && threadIdx.x < 8) g_cnts[threadIdx.x * 32] = 0u;
    int idx = blockIdx.x * 256 + threadIdx.x;
    const int n1 = 768 * 304;
    if (idx < n1) {
        int n = idx / 304, k = idx - n * 304;
        g_WihT[idx] = W_ih[k * 768 + n];
    } else {
        int r = idx - n1;            // exact grid: r < 768*256
        int n = r >> 8, k = r & 255;
        g_WhhT[r] = W_hh[k * 768 + n];
    }
}

// build Wcat[288][1024]
__global__ void prep2_kernel(const float* __restrict__ prior_W1, const float* __restrict__ prior_b1,
                             const float* __restrict__ dobs_W1,  const float* __restrict__ dobs_b1,
                             const float* __restrict__ drew_W1,  const float* __restrict__ drew_b1,
                             const float* __restrict__ dcont_W1, const float* __restrict__ dcont_b1)
{
    int idx = blockIdx.x * 256 + threadIdx.x;      // 288*1024 grid
    int k = idx >> 10, j = idx & 1023;
    int g = j >> 8, jj = j & 255;
    float v;
    if (g == 0)      v = (k < 256) ? prior_W1[k * 256 + jj] : 0.f;
    else if (g == 1) v = dobs_W1[(size_t)k * 256 + jj];
    else if (g == 2) v = drew_W1[(size_t)k * 256 + jj];
    else             v = dcont_W1[(size_t)k * 256 + jj];
    g_Wcat[idx] = v;
    if (idx < 1024) {
        float b;
        if (g == 0)      b = prior_b1[jj];
        else if (g == 1) b = dobs_b1[jj];
        else if (g == 2) b = drew_b1[jj];
        else             b = dcont_b1[jj];
        g_bcat[idx] = b;
    }
}

// ---------------- scoped-atomic group barrier (no MEMBAR.GL anywhere) ----------------
// caller pattern: __syncthreads(); bar_arrive(cnt); <overlapped work>; bar_wait(cnt, target);
__device__ __forceinline__ void bar_arrive(unsigned* cnt) {
    if (threadIdx.x == 0)
        asm volatile("red.release.gpu.global.add.u32 [%0], %1;" :: "l"(cnt), "r"(1u) : "memory");
}
__device__ __forceinline__ void bar_wait(unsigned* cnt, unsigned target) {
    if (threadIdx.x == 0) {
        unsigned v;
        do {
            asm volatile("ld.acquire.gpu.global.u32 %0, [%1];" : "=r"(v) : "l"(cnt) : "memory");
        } while (v < target);
    }
    __syncthreads();
}

// ---------------- persistent scan kernel ----------------
// 128 CTAs x 256 threads. CTA c: jt = c & 15 (16 h-cols), bt = c >> 4 (16 batch rows).
// 8 independent bt-groups; all sync intra-group via scoped atomics.
#define SM_WGRU 0
#define SM_W1H  26880
#define SM_W2   (SM_W1H + 16*260)           // 31040
#define SM_B2   (SM_W2 + 16384)             // 47424
#define SM_XS   (SM_B2 + 64)                // 47488  (xs: 16 x 308)
#define SM_HST  (SM_XS + 16*308)            // 52416  (hstage/hidl: 16 x 17)
#define SM_O64  (SM_HST + 16*17)            // 52688  (o64s: 16 x 64)
#define SM_STG  (SM_O64 + 1024)             // 53712  (pm/ps/z staging: 16 x 96)
#define SM_EBUF (SM_STG + 16*96)            // 55248  (eps prefetch: 512)
#define SM_ABUF (SM_EBUF + 512)             // 55760  (act prefetch: 256)
#define SM_FLOATS (SM_ABUF + 256)           // 56016
#define SMEM_BYTES (SM_FLOATS * 4)          // 224064

__global__ void __launch_bounds__(256, 1) scan_kernel(
    float* __restrict__ out, const float* __restrict__ act_seq,
    const float* __restrict__ eps,
    const float* __restrict__ b_ih, const float* __restrict__ b_hh,
    const float* __restrict__ post_W1, const float* __restrict__ post_W2,
    const float* __restrict__ post_b2)
{
    extern __shared__ float sm[];
    float* wgru = sm + SM_WGRU;
    float* w1hs = sm + SM_W1H;   // [jl][k] stride 260
    float* w2s  = sm + SM_W2;    // [k][o] 256x64
    float* b2s  = sm + SM_B2;
    float* xs   = sm + SM_XS;    // [16][308]: h(256) z(32) a(16); reused as hs [16][260]
    float* hst  = sm + SM_HST;   // [16][17]: hstage / hidl
    float* o64s = sm + SM_O64;   // [16][64]
    float* stg  = sm + SM_STG;   // [16][96] pm/ps/z staging (jt==0 only)
    float* ebuf = sm + SM_EBUF;  // [512] eps prefetch
    float* abuf = sm + SM_ABUF;  // [256] act prefetch

    const int tid = threadIdx.x;
    const int c   = blockIdx.x;
    const int jt  = c & 15;
    const int bt  = c >> 4;
    const int jl  = tid >> 4;
    const int bl  = tid & 15;
    const int jc  = jt * 16 + jl;
    const int b_a = bt * 16 + bl;
    unsigned* cnt = &g_cnts[bt * 32];

    // ---- preload weights into SMEM (once) ----
    for (int idx = tid; idx < 16 * 1680; idx += 256) {
        int j_ = idx / 1680, r = idx - j_ * 1680;
        int j = jt * 16 + j_;
        float v;
        if (r < 912) { int g = r / 304, k = r - g * 304; v = g_WihT[(size_t)(g * 256 + j) * 304 + k]; }
        else { int r2 = r - 912; int g = r2 >> 8, k = r2 & 255; v = g_WhhT[(size_t)(g * 256 + j) * 256 + k]; }
        wgru[idx] = v;
    }
    for (int idx = tid; idx < 16 * 256; idx += 256) {
        int j_ = idx >> 8, k = idx & 255;
        w1hs[j_ * 260 + k] = post_W1[(size_t)k * 256 + jt * 16 + j_];
    }
    for (int idx = tid; idx < 16384; idx += 256) w2s[idx] = post_W2[idx];
    if (tid < 64) b2s[tid] = post_b2[tid];
    __syncthreads();

    const float bir = b_ih[jc], biz = b_ih[jc + 256], bin_ = b_ih[jc + 512];
    const float bhr = b_hh[jc], bhz = b_hh[jc + 256], bhn = b_hh[jc + 512];

    unsigned barv = 0;

    for (int t = 0; t < T_STEPS; t++) {
        // register-prefetch oproj for this step's phase BC (hidden behind phase A)
        float oproj_reg = g_oproj[((size_t)b_a * T_STEPS + t) * 256 + jc];

        // ========== Phase A ==========
        if (t == 0) {
            int b_l = tid >> 4, j_l = tid & 15;
            g_state[(bt * 16 + b_l) * 256 + jt * 16 + j_l] = 0.f;
            __syncthreads();
            barv += 16; bar_arrive(cnt);
            out[((size_t)(bt * 16 + b_l) * T_STEPS + 0) * OUT_D + jt * 16 + j_l] = 0.f;
            bar_wait(cnt, barv);
        } else {
            // --- (a) independent L2 loads: o64 partial reduce + h for xs ---
            int b_l = tid >> 4, og = (tid & 15) * 4;
            float4 racc = *(const float4*)(b2s + og);
#pragma unroll
            for (int q = 0; q < 16; q++) {
                float4 v = ldcg4(g_part + ((size_t)(bt * 16 + b_l) * 16 + q) * 64 + og);
                racc.x += v.x; racc.y += v.y; racc.z += v.z; racc.w += v.w;
            }
            float4 hv[4];
#pragma unroll
            for (int p = 0; p < 4; p++) {
                int idx = tid + p * 256;           // 16*64 float4 slots
                int bl_ = idx >> 6, k4 = idx & 63;
                hv[p] = ldcg4(g_state + (bt * 16 + bl_) * 256 + k4 * 4);
            }
            // --- (b) stores to smem ---
            *(float4*)(o64s + b_l * 64 + og) = racc;
#pragma unroll
            for (int p = 0; p < 4; p++) {
                int idx = tid + p * 256;
                int bl_ = idx >> 6, k4 = idx & 63;
                *(float4*)(xs + bl_ * 308 + k4 * 4) = hv[p];
            }
            xs[(tid >> 4) * 308 + 288 + (tid & 15)] = abuf[tid];   // act from prefetch
            __syncthreads();
            // --- (c) sample z_{t-1} (eps from prefetch), stage outputs ---
            for (int idx = tid; idx < 512; idx += 256) {
                int bl_ = idx >> 5, s = idx & 31;
                float pm = o64s[bl_ * 64 + s];
                float ps = softplusf_(o64s[bl_ * 64 + 32 + s]) + 0.1f;
                float e  = ebuf[bl_ * 32 + s];
                float z  = fmaf(ps, e, pm);
                xs[bl_ * 308 + 256 + s] = z;
                if (jt == 0) {
                    stg[bl_ * 96 + s]      = pm;
                    stg[bl_ * 96 + 32 + s] = ps;
                    stg[bl_ * 96 + 64 + s] = z;
                }
            }
            __syncthreads();

            // --- (d) GRU with packed f32x2 FMAs ---
            const ulonglong2* xv  = (const ulonglong2*)(xs + bl * 308);
            const ulonglong2* wir = (const ulonglong2*)(wgru + jl * 1680);
            const ulonglong2* wiz = (const ulonglong2*)(wgru + jl * 1680 + 304);
            const ulonglong2* win = (const ulonglong2*)(wgru + jl * 1680 + 608);
            const ulonglong2* whr = (const ulonglong2*)(wgru + jl * 1680 + 912);
            const ulonglong2* whz = (const ulonglong2*)(wgru + jl * 1680 + 1168);
            const ulonglong2* whn = (const ulonglong2*)(wgru + jl * 1680 + 1424);

            ull air0=0, air1=0, aiz0=0, aiz1=0, ain0=0, ain1=0;
            ull ahr0=0, ahr1=0, ahz0=0, ahz1=0, ahn0=0, ahn1=0;
#pragma unroll 4
            for (int k4 = 0; k4 < 64; k4++) {
                ulonglong2 x2 = xv[k4];
                ulonglong2 w;
                w = wir[k4]; fma2(air0, x2.x, w.x); fma2(air1, x2.y, w.y);
                w = wiz[k4]; fma2(aiz0, x2.x, w.x); fma2(aiz1, x2.y, w.y);
                w = win[k4]; fma2(ain0, x2.x, w.x); fma2(ain1, x2.y, w.y);
                w = whr[k4]; fma2(ahr0, x2.x, w.x); fma2(ahr1, x2.y, w.y);
                w = whz[k4]; fma2(ahz0, x2.x, w.x); fma2(ahz1, x2.y, w.y);
                w = whn[k4]; fma2(ahn0, x2.x, w.x); fma2(ahn1, x2.y, w.y);
            }
#pragma unroll
            for (int k4 = 64; k4 < 76; k4++) {   // z,a feed only input gates
                ulonglong2 x2 = xv[k4];
                ulonglong2 w;
                w = wir[k4]; fma2(air0, x2.x, w.x); fma2(air1, x2.y, w.y);
                w = wiz[k4]; fma2(aiz0, x2.x, w.x); fma2(aiz1, x2.y, w.y);
                w = win[k4]; fma2(ain0, x2.x, w.x); fma2(ain1, x2.y, w.y);
            }
            add2(air0, air1); add2(aiz0, aiz1); add2(ain0, ain1);
            add2(ahr0, ahr1); add2(ahz0, ahz1); add2(ahn0, ahn1);
            float2 fr = unpack2(air0), fz = unpack2(aiz0), fn = unpack2(ain0);
            float2 gr = unpack2(ahr0), gz = unpack2(ahz0), gn = unpack2(ahn0);
            float sir = fr.x + fr.y + bir;
            float siz = fz.x + fz.y + biz;
            float sin_= fn.x + fn.y + bin_;
            float shr = gr.x + gr.y + bhr;
            float shz = gz.x + gz.y + bhz;
            float shn = gn.x + gn.y + bhn;

            float r  = sigmoidf_(sir + shr);
            float zg = sigmoidf_(siz + shz);
            float n  = tanhf(sin_ + r * shn);
            float hprev = xs[bl * 308 + jc];
            float hnew  = (1.f - zg) * n + zg * hprev;
            hst[bl * 17 + jl] = hnew;
            __syncthreads();
            // --- (e) coalesced g_state write (consumed cross-CTA) ---
            {
                int b_l2 = tid >> 4, j_l = tid & 15;
                g_state[(bt * 16 + b_l2) * 256 + jt * 16 + j_l] = hst[b_l2 * 17 + j_l];
            }
            __syncthreads();
            barv += 16; bar_arrive(cnt);
            // --- (f) deferred out writes, overlapped with barrier poll ---
            {
                int b_l2 = tid >> 4, j_l = tid & 15;
                out[((size_t)(bt * 16 + b_l2) * T_STEPS + t) * OUT_D + jt * 16 + j_l] =
                    hst[b_l2 * 17 + j_l];
            }
            if (jt == 0) {
                for (int idx = tid; idx < 512; idx += 256) {
                    int bl_ = idx >> 5, s = idx & 31;
                    size_t base = ((size_t)(bt * 16 + bl_) * T_STEPS + (t - 1)) * OUT_D;
                    out[base + 352 + s] = stg[bl_ * 96 + s];
                    out[base + 384 + s] = stg[bl_ * 96 + 32 + s];
                    out[base + 256 + s] = stg[bl_ * 96 + 64 + s];
                }
            }
            bar_wait(cnt, barv);
        }

        // ========== Phase BC: hid slice + partial o64 ==========
        {
            float* hs = xs;   // [16][260]
#pragma unroll
            for (int p = 0; p < 4; p++) {
                int idx = tid + p * 256;
                int b_l = idx >> 6, k4 = idx & 63;
                float4 v = ldcg4(g_state + (bt * 16 + b_l) * 256 + k4 * 4);
                *(float4*)(hs + b_l * 260 + k4 * 4) = v;
            }
            __syncthreads();
            const ulonglong2* hv2 = (const ulonglong2*)(hs + bl * 260);
            const ulonglong2* wv2 = (const ulonglong2*)(w1hs + jl * 260);
            ull a0 = 0, a1 = 0;
#pragma unroll 8
            for (int k4 = 0; k4 < 64; k4++) {
                ulonglong2 h2 = hv2[k4], w2v = wv2[k4];
                fma2(a0, h2.x, w2v.x);
                fma2(a1, h2.y, w2v.y);
            }
            add2(a0, a1);
            float2 f = unpack2(a0);
            float acc = f.x + f.y + oproj_reg;
            hst[bl * 17 + jl] = fmaxf(acc, 0.f);   // hidl
            __syncthreads();
            // partial o64: rank-16 update with W2 rows [jt*16, jt*16+16)
            const int o = tid & 63, bq = tid >> 6;
#pragma unroll
            for (int bb = 0; bb < 4; bb++) {
                int b_l = bq * 4 + bb;
                float pacc = 0.f;
#pragma unroll
                for (int k = 0; k < 16; k++)
                    pacc = fmaf(hst[b_l * 17 + k], w2s[(jt * 16 + k) * 64 + o], pacc);
                g_part[((size_t)(bt * 16 + b_l) * 16 + jt) * 64 + o] = pacc;
            }
            __syncthreads();
            barv += 16; bar_arrive(cnt);
            // --- prefetch next step's eps/act into smem, overlapped with poll ---
            {
                float2 ev = *(const float2*)(eps + ((size_t)t * B_SZ + bt * 16) * 32 + tid * 2);
                *(float2*)(ebuf + tid * 2) = ev;
                abuf[tid] = act_seq[((size_t)(bt * 16 + (tid >> 4)) * T_STEPS + t) * 16 + (tid & 15)];
            }
            bar_wait(cnt, barv);
        }
    }

    // ========== epilogue: reduce partials for t=511, write outputs ==========
    {
        const int b = c;                       // one batch row per CTA (same bt-group)
        if (tid < 64) {
            float acc = b2s[tid];
#pragma unroll
            for (int q = 0; q < 16; q++)
                acc += ldcg1(g_part + ((size_t)b * 16 + q) * 64 + tid);
            o64s[tid] = acc;
        }
        __syncthreads();
        if (tid < 32) {
            int s = tid;
            float pm = o64s[s];
            float ps = softplusf_(o64s[32 + s]) + 0.1f;
            float e  = eps[((size_t)(T_STEPS - 1) * B_SZ + b) * 32 + s];
            float z  = fmaf(ps, e, pm);
            size_t base = ((size_t)b * T_STEPS + (T_STEPS - 1)) * OUT_D;
            out[base + 352 + s] = pm;
            out[base + 384 + s] = ps;
            out[base + 256 + s] = z;
        }
    }
}

// ---------------- fp32 tiled GEMM with f32x2: C = act(A@W + bias) ----------------
__global__ void gemm_kernel(int M, int N, int K,
                            const float* __restrict__ A, int lda,
                            const float* __restrict__ W,
                            const float* __restrict__ bias,
                            float* __restrict__ C, int ldc, int act)
{
    __shared__ __align__(16) float As[16][132];
    __shared__ __align__(16) float Ws[16][64];
    const int tid = threadIdx.x;
    const int tx = tid & 15;
    const int ty = tid >> 4;
    const int rowBase = blockIdx.y * 128;
    const int colBase = blockIdx.x * 64;

    ull acc2[4][4];
#pragma unroll
    for (int p = 0; p < 4; p++)
#pragma unroll
        for (int j = 0; j < 4; j++) acc2[p][j] = 0ull;

    const int ka = tid & 15;
    const int ra = tid >> 4;
    const int nw = tid & 63;
    const int kw = tid >> 6;

    for (int k0 = 0; k0 < K; k0 += 16) {
#pragma unroll
        for (int p = 0; p < 8; p++)
            As[ka][ra + p * 16] = A[(size_t)(rowBase + ra + p * 16) * lda + k0 + ka];
#pragma unroll
        for (int p = 0; p < 4; p++)
            Ws[kw + p * 4][nw] = W[(size_t)(k0 + kw + p * 4) * N + colBase + nw];
        __syncthreads();
#pragma unroll
        for (int k = 0; k < 16; k++) {
            ulonglong2 A01 = *(const ulonglong2*)&As[k][ty * 8];
            ulonglong2 A23 = *(const ulonglong2*)&As[k][ty * 8 + 4];
            float4 wv = *(const float4*)&Ws[k][tx * 4];
            ull wd0 = pack2(wv.x, wv.x), wd1 = pack2(wv.y, wv.y);
            ull wd2 = pack2(wv.z, wv.z), wd3 = pack2(wv.w, wv.w);
            fma2(acc2[0][0], A01.x, wd0); fma2(acc2[0][1], A01.x, wd1);
            fma2(acc2[0][2], A01.x, wd2); fma2(acc2[0][3], A01.x, wd3);
            fma2(acc2[1][0], A01.y, wd0); fma2(acc2[1][1], A01.y, wd1);
            fma2(acc2[1][2], A01.y, wd2); fma2(acc2[1][3], A01.y, wd3);
            fma2(acc2[2][0], A23.x, wd0); fma2(acc2[2][1], A23.x, wd1);
            fma2(acc2[2][2], A23.x, wd2); fma2(acc2[2][3], A23.x, wd3);
            fma2(acc2[3][0], A23.y, wd0); fma2(acc2[3][1], A23.y, wd1);
            fma2(acc2[3][2], A23.y, wd2); fma2(acc2[3][3], A23.y, wd3);
        }
        __syncthreads();
    }
#pragma unroll
    for (int p = 0; p < 4; p++) {
#pragma unroll
        for (int j = 0; j < 4; j++) {
            float2 f = unpack2(acc2[p][j]);
            int cc = colBase + tx * 4 + j;
            float bval = bias ? bias[cc] : 0.f;
            float v0 = f.x + bval;
            float v1 = f.y + bval;
            if (act == 1) { v0 = fmaxf(v0, 0.f); v1 = fmaxf(v1, 0.f); }
            else if (act == 2 && cc >= 32) {
                v0 = softplusf_(v0) + 0.1f;
                v1 = softplusf_(v1) + 0.1f;
            }
            int r0 = rowBase + ty * 8 + 2 * p;
            C[(size_t)r0 * ldc + cc] = v0;
            C[(size_t)(r0 + 1) * ldc + cc] = v1;
        }
    }
}

// ---------------- GEMV (N=1): K=256 ----------------
__global__ void gemv_kernel(const float* __restrict__ A, int lda,
                            const float* __restrict__ w,
                            const float* __restrict__ bias, float* __restrict__ C, int act)
{
    const int warp = threadIdx.x >> 5, lane = threadIdx.x & 31;
    const int row = blockIdx.x * 8 + warp;
    const float* a = A + (size_t)row * lda;
    float acc = 0.f;
#pragma unroll
    for (int i = 0; i < 8; i++) acc = fmaf(a[lane + 32 * i], w[lane + 32 * i], acc);
#pragma unroll
    for (int off = 16; off; off >>= 1) acc += __shfl_xor_sync(0xffffffffu, acc, off);
    if (lane == 0) {
        float v = acc + bias[0];
        if (act == 3) v = sigmoidf_(v);
        C[(size_t)row * OUT_D] = v;
    }
}

// ---------------- driver ----------------
extern "C" void kernel_launch(void* const* d_in, const int* in_sizes, int n_in,
                              void* d_out, int out_size)
{
    const float* obs      = (const float*)d_in[0];
    const float* act      = (const float*)d_in[1];
    const float* eps      = (const float*)d_in[2];
    const float* prior_W1 = (const float*)d_in[3];
    const float* prior_b1 = (const float*)d_in[4];
    const float* prior_W2 = (const float*)d_in[5];
    const float* prior_b2 = (const float*)d_in[6];
    const float* post_W1  = (const float*)d_in[7];
    const float* post_b1  = (const float*)d_in[8];
    const float* post_W2  = (const float*)d_in[9];
    const float* post_b2  = (const float*)d_in[10];
    const float* W_ih     = (const float*)d_in[11];
    const float* b_ih     = (const float*)d_in[12];
    const float* W_hh     = (const float*)d_in[13];
    const float* b_hh     = (const float*)d_in[14];
    const float* dobs_W1  = (const float*)d_in[15];
    const float* dobs_b1  = (const float*)d_in[16];
    const float* dobs_W2  = (const float*)d_in[17];
    const float* dobs_b2  = (const float*)d_in[18];
    const float* drew_W1  = (const float*)d_in[19];
    const float* drew_b1  = (const float*)d_in[20];
    const float* drew_W2  = (const float*)d_in[21];
    const float* drew_b2  = (const float*)d_in[22];
    const float* dcont_W1 = (const float*)d_in[23];
    const float* dcont_b1 = (const float*)d_in[24];
    const float* dcont_W2 = (const float*)d_in[25];
    const float* dcont_b2 = (const float*)d_in[26];
    float* out = (float*)d_out;

    float *oproj_p = nullptr, *hid3_p = nullptr, *wcat_p = nullptr, *bcat_p = nullptr;
    cudaGetSymbolAddress((void**)&oproj_p, g_oproj);
    cudaGetSymbolAddress((void**)&hid3_p, g_hid3);
    cudaGetSymbolAddress((void**)&wcat_p, g_Wcat);
    cudaGetSymbolAddress((void**)&bcat_p, g_bcat);

    static int smem_set = 0;
    if (!smem_set) {
        cudaFuncSetAttribute(scan_kernel, cudaFuncAttributeMaxDynamicSharedMemorySize, SMEM_BYTES);
        smem_set = 1;
    }

    prep_kernel<<<1680, 256>>>(W_ih, W_hh);
    prep2_kernel<<<1152, 256>>>(prior_W1, prior_b1, dobs_W1, dobs_b1,
                                drew_W1, drew_b1, dcont_W1, dcont_b1);

    // Phase A: o_proj = obs @ W1o + post_b1  (rows 256..1279 of post_W1)
    gemm_kernel<<<dim3(4, BT / 128), 256>>>(BT, 256, 1024, obs, 1024,
                                            post_W1 + 256 * 256, post_b1,
                                            oproj_p, 256, 0);

    // Phase B: persistent sequential scan (GRU + posterior + sample)
    scan_kernel<<<NCTA, 256, SMEM_BYTES>>>(out, act, eps, b_ih, b_hh,
                                           post_W1, post_W2, post_b2);

    // Phase C: merged decoder/prior L1: hid3 = relu([h,z] @ Wcat + bcat)
    gemm_kernel<<<dim3(16, BT / 128), 256>>>(BT, 1024, 288, out, OUT_D,
                                             wcat_p, bcat_p, hid3_p, 1024, 1);
    // prior L2 (cols 0..255 of hid3)
    gemm_kernel<<<dim3(1, BT / 128), 256>>>(BT, 64, 256, hid3_p, 1024,
                                            prior_W2, prior_b2, out + 288, OUT_D, 2);
    // obs decoder L2 (cols 256..511)
    gemm_kernel<<<dim3(16, BT / 128), 256>>>(BT, 1024, 256, hid3_p + 256, 1024,
                                             dobs_W2, dobs_b2, out + 416, OUT_D, 0);
    // reward (cols 512..767) / continuation (cols 768..1023)
    gemv_kernel<<<BT / 8, 256>>>(hid3_p + 512, 1024, drew_W2, drew_b2, out + 1440, 0);
    gemv_kernel<<<BT / 8, 256>>>(hid3_p + 768, 1024, dcont_W2, dcont_b2, out + 1441, 3);
}